// round 1
// baseline (speedup 1.0000x reference)
#include <cuda_runtime.h>
#include <cuda_bf16.h>
#include <math.h>

// Problem constants
#define BATCH 4
#define SEQ   2048
#define CDIM  768
#define NHEAD 12
#define HDIM  64
#define MROWS (BATCH*SEQ)        // 8192
#define QKVDIM (3*CDIM)          // 2304
#define FCDIM  (4*CDIM)          // 3072

// ---------------- device scratch (no allocations allowed) ----------------
__device__ float g_ln [MROWS*CDIM];     // 25 MB (reused for ln1 and ln2)
__device__ float g_qkv[MROWS*QKVDIM];   // 75 MB
__device__ float g_att[MROWS*CDIM];     // 25 MB
__device__ float g_x1 [MROWS*CDIM];     // 25 MB
__device__ float g_fc [MROWS*FCDIM];    // 100 MB

// ---------------- LayerNorm: one block per row ----------------
__global__ __launch_bounds__(256)
void ln_kernel(const float* __restrict__ x, const float* __restrict__ gw,
               const float* __restrict__ gb, float* __restrict__ out)
{
    int row = blockIdx.x;
    const float* xr = x + (size_t)row * CDIM;
    float s = 0.f, s2 = 0.f;
    for (int i = threadIdx.x; i < CDIM; i += 256) {
        float t = xr[i]; s += t; s2 += t * t;
    }
    #pragma unroll
    for (int o = 16; o; o >>= 1) {
        s  += __shfl_xor_sync(0xFFFFFFFFu, s,  o);
        s2 += __shfl_xor_sync(0xFFFFFFFFu, s2, o);
    }
    __shared__ float ss[8], ss2[8];
    int wid = threadIdx.x >> 5, lane = threadIdx.x & 31;
    if (lane == 0) { ss[wid] = s; ss2[wid] = s2; }
    __syncthreads();
    if (threadIdx.x == 0) {
        float a = 0.f, a2 = 0.f;
        #pragma unroll
        for (int i = 0; i < 8; i++) { a += ss[i]; a2 += ss2[i]; }
        ss[0] = a; ss2[0] = a2;
    }
    __syncthreads();
    float mean = ss[0] * (1.f / CDIM);
    float var  = ss2[0] * (1.f / CDIM) - mean * mean;
    var = fmaxf(var, 0.f);
    float inv = 1.f / (sqrtf(var) + 1e-6f);
    float* orow = out + (size_t)row * CDIM;
    for (int i = threadIdx.x; i < CDIM; i += 256)
        orow[i] = gw[i] * (xr[i] - mean) * inv + gb[i];
}

// ---------------- SGEMM: C[M,N] = A[M,K] @ B[K,N] + bias (+epilogue) ------
// EPI: 0 = bias only, 1 = bias + exact GELU, 2 = bias + residual add
// Tiles: 128x128x8, 256 threads, 8x8 per-thread micro-tile.
// Assumes M%128==0, N%128==0, K%8==0 (true for all calls here).
template<int EPI>
__global__ __launch_bounds__(256)
void gemm_kernel(const float* __restrict__ A, const float* __restrict__ B,
                 const float* __restrict__ bias, const float* __restrict__ res,
                 float* __restrict__ C, int M, int N, int K)
{
    __shared__ float As[8][132];   // transposed: As[k][m], padded
    __shared__ float Bs[8][128];

    int tid  = threadIdx.x;
    int row0 = blockIdx.y * 128;
    int col0 = blockIdx.x * 128;

    int ar = tid >> 1;           // 0..127
    int ac = (tid & 1) * 4;      // 0 or 4
    int br = tid >> 5;           // 0..7
    int bc = (tid & 31) * 4;     // 0..124
    int tm = (tid >> 4) * 8;     // 0..120
    int tn = (tid & 15) * 8;     // 0..120

    const float* Aptr = A + (size_t)(row0 + ar) * K + ac;
    const float* Bptr = B + (size_t)br * N + col0 + bc;

    float acc[8][8];
    #pragma unroll
    for (int i = 0; i < 8; i++)
        #pragma unroll
        for (int j = 0; j < 8; j++) acc[i][j] = 0.f;

    for (int kt = 0; kt < K; kt += 8) {
        float4 av = *(const float4*)(Aptr + kt);
        float4 bv = *(const float4*)(Bptr + (size_t)kt * N);
        As[ac + 0][ar] = av.x;
        As[ac + 1][ar] = av.y;
        As[ac + 2][ar] = av.z;
        As[ac + 3][ar] = av.w;
        *(float4*)&Bs[br][bc] = bv;
        __syncthreads();
        #pragma unroll
        for (int k = 0; k < 8; k++) {
            float a[8], b[8];
            *(float4*)(a)     = *(const float4*)&As[k][tm];
            *(float4*)(a + 4) = *(const float4*)&As[k][tm + 4];
            *(float4*)(b)     = *(const float4*)&Bs[k][tn];
            *(float4*)(b + 4) = *(const float4*)&Bs[k][tn + 4];
            #pragma unroll
            for (int i = 0; i < 8; i++)
                #pragma unroll
                for (int j = 0; j < 8; j++)
                    acc[i][j] += a[i] * b[j];
        }
        __syncthreads();
    }

    #pragma unroll
    for (int i = 0; i < 8; i++) {
        int row = row0 + tm + i;
        #pragma unroll
        for (int j = 0; j < 8; j++) {
            int col = col0 + tn + j;
            float v = acc[i][j] + bias[col];
            if (EPI == 1) {
                v = 0.5f * v * (1.f + erff(v * 0.7071067811865475f));
            } else if (EPI == 2) {
                v += res[(size_t)row * N + col];
            }
            C[(size_t)row * N + col] = v;
        }
    }
}

// ---------------- Flash attention (causal, fp32) ----------------
// grid: (SEQ/128, NHEAD, BATCH), block: 128 threads; 1 thread = 1 query row.
__global__ __launch_bounds__(128)
void attn_kernel(const float* __restrict__ qkv, float* __restrict__ out)
{
    int b = blockIdx.z, h = blockIdx.y;
    int qi = blockIdx.x * 128 + threadIdx.x;   // 0..2047 (always in range)

    __shared__ float Ks[64][64];
    __shared__ float Vs[64][64];

    const float* base = qkv + (size_t)b * SEQ * QKVDIM;
    const float* qrow = base + (size_t)qi * QKVDIM + h * HDIM;
    const float scale = 0.125f;   // 1/sqrt(64)

    float q[HDIM];
    #pragma unroll
    for (int d = 0; d < HDIM; d += 4) {
        float4 t = *(const float4*)(qrow + d);
        q[d] = t.x * scale; q[d+1] = t.y * scale; q[d+2] = t.z * scale; q[d+3] = t.w * scale;
    }

    float acc[HDIM];
    #pragma unroll
    for (int d = 0; d < HDIM; d++) acc[d] = 0.f;
    float m = -1e30f, l = 0.f;

    int ntiles = blockIdx.x * 2 + 2;           // key tiles of 64 needed by this block
    int jr = threadIdx.x >> 1;                 // 0..63
    int c0 = (threadIdx.x & 1) * 32;

    for (int kt = 0; kt < ntiles; kt++) {
        __syncthreads();
        const float* krow = base + (size_t)(kt * 64 + jr) * QKVDIM + CDIM + h * HDIM + c0;
        const float* vrow = krow + CDIM;
        #pragma unroll
        for (int c = 0; c < 32; c += 4) {
            *(float4*)&Ks[jr][c0 + c] = *(const float4*)(krow + c);
            *(float4*)&Vs[jr][c0 + c] = *(const float4*)(vrow + c);
        }
        __syncthreads();

        int jmax = qi - kt * 64 + 1;
        if (jmax > 64) jmax = 64;
        for (int j = 0; j < jmax; j++) {
            float s0 = 0.f, s1 = 0.f, s2 = 0.f, s3 = 0.f;
            #pragma unroll
            for (int d = 0; d < HDIM; d += 4) {
                s0 += q[d]     * Ks[j][d];
                s1 += q[d + 1] * Ks[j][d + 1];
                s2 += q[d + 2] * Ks[j][d + 2];
                s3 += q[d + 3] * Ks[j][d + 3];
            }
            float s = (s0 + s1) + (s2 + s3);
            if (s <= m) {
                float p = __expf(s - m);
                l += p;
                #pragma unroll
                for (int d = 0; d < HDIM; d++) acc[d] += p * Vs[j][d];
            } else {
                float corr = __expf(m - s);
                m = s;
                l = l * corr + 1.f;
                #pragma unroll
                for (int d = 0; d < HDIM; d++) acc[d] = acc[d] * corr + Vs[j][d];
            }
        }
    }

    float inv = 1.f / l;
    float* orow = out + ((size_t)(b * SEQ + qi)) * CDIM + h * HDIM;
    #pragma unroll
    for (int d = 0; d < HDIM; d += 4) {
        float4 t;
        t.x = acc[d] * inv; t.y = acc[d+1] * inv; t.z = acc[d+2] * inv; t.w = acc[d+3] * inv;
        *(float4*)(orow + d) = t;
    }
}

// ---------------- launch ----------------
extern "C" void kernel_launch(void* const* d_in, const int* in_sizes, int n_in,
                              void* d_out, int out_size)
{
    const float* x           = (const float*)d_in[0];
    const float* ln1_w       = (const float*)d_in[1];
    const float* ln1_b       = (const float*)d_in[2];
    const float* W_attn      = (const float*)d_in[3];
    const float* b_attn      = (const float*)d_in[4];
    const float* W_attn_proj = (const float*)d_in[5];
    const float* b_attn_proj = (const float*)d_in[6];
    const float* ln2_w       = (const float*)d_in[7];
    const float* ln2_b       = (const float*)d_in[8];
    const float* W_fc        = (const float*)d_in[9];
    const float* b_fc        = (const float*)d_in[10];
    const float* W_mlp_proj  = (const float*)d_in[11];
    const float* b_mlp_proj  = (const float*)d_in[12];
    float* out = (float*)d_out;

    float *p_ln, *p_qkv, *p_att, *p_x1, *p_fc;
    cudaGetSymbolAddress((void**)&p_ln,  g_ln);
    cudaGetSymbolAddress((void**)&p_qkv, g_qkv);
    cudaGetSymbolAddress((void**)&p_att, g_att);
    cudaGetSymbolAddress((void**)&p_x1,  g_x1);
    cudaGetSymbolAddress((void**)&p_fc,  g_fc);

    // 1. h = LN1(x)
    ln_kernel<<<MROWS, 256>>>(x, ln1_w, ln1_b, p_ln);
    // 2. qkv = h @ W_attn + b_attn          [8192 x 2304]
    gemm_kernel<0><<<dim3(QKVDIM/128, MROWS/128), 256>>>(p_ln, W_attn, b_attn, nullptr, p_qkv, MROWS, QKVDIM, CDIM);
    // 3. y = causal_attention(qkv)          [8192 x 768]
    attn_kernel<<<dim3(SEQ/128, NHEAD, BATCH), 128>>>(p_qkv, p_att);
    // 4. x1 = x + y @ W_attn_proj + b       [8192 x 768]
    gemm_kernel<2><<<dim3(CDIM/128, MROWS/128), 256>>>(p_att, W_attn_proj, b_attn_proj, x, p_x1, MROWS, CDIM, CDIM);
    // 5. h = LN2(x1)
    ln_kernel<<<MROWS, 256>>>(p_x1, ln2_w, ln2_b, p_ln);
    // 6. fc = gelu(h @ W_fc + b_fc)         [8192 x 3072]
    gemm_kernel<1><<<dim3(FCDIM/128, MROWS/128), 256>>>(p_ln, W_fc, b_fc, nullptr, p_fc, MROWS, FCDIM, CDIM);
    // 7. out = x1 + fc @ W_mlp_proj + b     [8192 x 768]
    gemm_kernel<2><<<dim3(CDIM/128, MROWS/128), 256>>>(p_fc, W_mlp_proj, b_mlp_proj, p_x1, out, MROWS, CDIM, FCDIM);
}

// round 4
// speedup vs baseline: 1.4845x; 1.4845x over previous
#include <cuda_runtime.h>
#include <cuda_bf16.h>
#include <stdint.h>
#include <math.h>

#define BATCH 4
#define SEQ   2048
#define CDIM  768
#define NHEAD 12
#define HDIM  64
#define MROWS 8192
#define QKVDIM 2304
#define FCDIM  3072

typedef __nv_bfloat16 bf16;

// ---------------- device scratch ----------------
__device__ bf16  g_lnh[MROWS*CDIM];
__device__ bf16  g_lnl[MROWS*CDIM];
__device__ float g_qkv[MROWS*QKVDIM];
__device__ bf16  g_atth[MROWS*CDIM];
__device__ bf16  g_attl[MROWS*CDIM];
__device__ float g_x1[MROWS*CDIM];
__device__ bf16  g_fch[MROWS*FCDIM];
__device__ bf16  g_fcl[MROWS*FCDIM];
__device__ bf16  g_wah[CDIM*QKVDIM];
__device__ bf16  g_wal[CDIM*QKVDIM];
__device__ bf16  g_wph[CDIM*CDIM];
__device__ bf16  g_wpl[CDIM*CDIM];
__device__ bf16  g_wfh[CDIM*FCDIM];
__device__ bf16  g_wfl[CDIM*FCDIM];
__device__ bf16  g_wmh[FCDIM*CDIM];
__device__ bf16  g_wml[FCDIM*CDIM];

__device__ __forceinline__ void split_bf16(float x, bf16* h, bf16* l)
{
    float hf = __bfloat162float(__float2bfloat16(x));
    *h = __float2bfloat16(x);
    *l = __float2bfloat16(x - hf);
}

// ---------------- fp32 -> hi/lo conversion ----------------
__global__ void cvt_kernel(const float* __restrict__ src, bf16* __restrict__ hi,
                           bf16* __restrict__ lo, int n)
{
    int i = blockIdx.x * 256 + threadIdx.x;
    if (i < n) {
        split_bf16(src[i], hi + i, lo + i);
    }
}

// ---------------- LayerNorm ----------------
__global__ __launch_bounds__(256) void ln_kernel(
    const float* __restrict__ x, const float* __restrict__ gw,
    const float* __restrict__ gb, bf16* __restrict__ oh, bf16* __restrict__ ol)
{
    __shared__ float ss[8];
    __shared__ float ss2[8];
    int row = blockIdx.x;
    const float* xr = x + (size_t)row * CDIM;
    float s = 0.f, s2 = 0.f;
    for (int i = threadIdx.x; i < CDIM; i += 256) {
        float t = xr[i];
        s += t;
        s2 += t * t;
    }
    for (int o = 16; o > 0; o >>= 1) {
        s  += __shfl_xor_sync(0xFFFFFFFFu, s,  o);
        s2 += __shfl_xor_sync(0xFFFFFFFFu, s2, o);
    }
    int wid = threadIdx.x >> 5;
    int lane = threadIdx.x & 31;
    if (lane == 0) {
        ss[wid] = s;
        ss2[wid] = s2;
    }
    __syncthreads();
    if (threadIdx.x == 0) {
        float a = 0.f, a2 = 0.f;
        for (int i = 0; i < 8; i++) {
            a += ss[i];
            a2 += ss2[i];
        }
        ss[0] = a;
        ss2[0] = a2;
    }
    __syncthreads();
    float mean = ss[0] * (1.f / CDIM);
    float var  = ss2[0] * (1.f / CDIM) - mean * mean;
    if (var < 0.f) var = 0.f;
    float inv = 1.f / (sqrtf(var) + 1e-6f);
    for (int i = threadIdx.x; i < CDIM; i += 256) {
        float v = gw[i] * (xr[i] - mean) * inv + gb[i];
        split_bf16(v, oh + (size_t)row * CDIM + i, ol + (size_t)row * CDIM + i);
    }
}

// ---------------- mma helpers (note: asm operand lists spaced to keep the
// template-render pipeline from seeing Jinja-style delimiters) ----------------
__device__ __forceinline__ void ldsm_x4(uint32_t* r, const void* p)
{
    uint32_t addr = (uint32_t)__cvta_generic_to_shared(p);
    asm volatile("ldmatrix.sync.aligned.m8n8.x4.shared.b16 { %0, %1, %2, %3 }, [ %4 ];"
        : "=r"(r[0]), "=r"(r[1]), "=r"(r[2]), "=r"(r[3]) : "r"(addr));
}

__device__ __forceinline__ void ldsm_x4_t(uint32_t* r, const void* p)
{
    uint32_t addr = (uint32_t)__cvta_generic_to_shared(p);
    asm volatile("ldmatrix.sync.aligned.m8n8.x4.trans.shared.b16 { %0, %1, %2, %3 }, [ %4 ];"
        : "=r"(r[0]), "=r"(r[1]), "=r"(r[2]), "=r"(r[3]) : "r"(addr));
}

__device__ __forceinline__ void mma_bf16(float* c, const uint32_t* a,
                                         uint32_t b0, uint32_t b1)
{
    asm volatile("mma.sync.aligned.m16n8k16.row.col.f32.bf16.bf16.f32 "
        "{ %0, %1, %2, %3 }, { %4, %5, %6, %7 }, { %8, %9 }, { %0, %1, %2, %3 };"
        : "+f"(c[0]), "+f"(c[1]), "+f"(c[2]), "+f"(c[3])
        : "r"(a[0]), "r"(a[1]), "r"(a[2]), "r"(a[3]), "r"(b0), "r"(b1));
}

// ---------------- split-bf16 tensor-core GEMM ----------------
// EPI: 0 = bias -> fp32,  1 = bias+GELU -> bf16 hi/lo,  2 = bias+residual -> fp32
template<int EPI>
__global__ __launch_bounds__(256, 2) void hgemm(
    const bf16* __restrict__ Ahi, const bf16* __restrict__ Alo,
    const bf16* __restrict__ Bhi, const bf16* __restrict__ Blo,
    const float* __restrict__ bias, const float* __restrict__ res,
    float* __restrict__ Cf, bf16* __restrict__ Chi, bf16* __restrict__ Clo,
    int M, int N, int K)
{
    __shared__ bf16 As[128][40];
    __shared__ bf16 Bs[32][136];

    const int tid  = threadIdx.x;
    const int lane = tid & 31;
    const int warp = tid >> 5;
    const int wm = (warp >> 1) * 32;
    const int wn = (warp & 1) * 64;
    const int row0 = blockIdx.y * 128;
    const int col0 = blockIdx.x * 128;

    const int rA0 = tid >> 2;
    const int cA0 = (tid & 3) * 8;
    const int rA1 = rA0 + 64;
    const int rB0 = tid >> 4;
    const int cB0 = (tid & 15) * 8;
    const int rB1 = rB0 + 16;

    const int KT = K / 32;
    const int NT = 3 * KT;

    float acc[2][8][4];
    for (int i = 0; i < 2; i++) {
        for (int j = 0; j < 8; j++) {
            for (int e = 0; e < 4; e++) {
                acc[i][j][e] = 0.f;
            }
        }
    }

    uint4 ra0, ra1, rb0, rb1;

    // prefetch tile 0 (phase 0: hi/hi)
    ra0 = *(const uint4*)(Ahi + (size_t)(row0 + rA0) * K + cA0);
    ra1 = *(const uint4*)(Ahi + (size_t)(row0 + rA1) * K + cA0);
    rb0 = *(const uint4*)(Bhi + (size_t)rB0 * N + col0 + cB0);
    rb1 = *(const uint4*)(Bhi + (size_t)rB1 * N + col0 + cB0);

    for (int it = 0; it < NT; ++it) {
        *(uint4*)&As[rA0][cA0] = ra0;
        *(uint4*)&As[rA1][cA0] = ra1;
        *(uint4*)&Bs[rB0][cB0] = rb0;
        *(uint4*)&Bs[rB1][cB0] = rb1;
        __syncthreads();

        if (it + 1 < NT) {
            int nit = it + 1;
            int ph = nit / KT;
            int kk = (nit % KT) * 32;
            const bf16* Ap = (ph == 1) ? Alo : Ahi;
            const bf16* Bp = (ph == 2) ? Blo : Bhi;
            ra0 = *(const uint4*)(Ap + (size_t)(row0 + rA0) * K + kk + cA0);
            ra1 = *(const uint4*)(Ap + (size_t)(row0 + rA1) * K + kk + cA0);
            rb0 = *(const uint4*)(Bp + (size_t)(kk + rB0) * N + col0 + cB0);
            rb1 = *(const uint4*)(Bp + (size_t)(kk + rB1) * N + col0 + cB0);
        }

        for (int ks = 0; ks < 2; ++ks) {
            const int k0 = ks * 16;
            uint32_t af0[4];
            uint32_t af1[4];
            ldsm_x4(af0, &As[wm + (lane & 15)][k0 + (lane >> 4) * 8]);
            ldsm_x4(af1, &As[wm + 16 + (lane & 15)][k0 + (lane >> 4) * 8]);
            for (int ni = 0; ni < 4; ++ni) {
                uint32_t bb[4];
                ldsm_x4_t(bb, &Bs[k0 + (lane & 15)][wn + ni * 16 + (lane >> 4) * 8]);
                mma_bf16(acc[0][ni * 2 + 0], af0, bb[0], bb[1]);
                mma_bf16(acc[0][ni * 2 + 1], af0, bb[2], bb[3]);
                mma_bf16(acc[1][ni * 2 + 0], af1, bb[0], bb[1]);
                mma_bf16(acc[1][ni * 2 + 1], af1, bb[2], bb[3]);
            }
        }
        __syncthreads();
    }

    for (int mi = 0; mi < 2; ++mi) {
        for (int n8 = 0; n8 < 8; ++n8) {
            for (int e = 0; e < 4; ++e) {
                int r = row0 + wm + mi * 16 + (lane >> 2) + (e >> 1) * 8;
                int c = col0 + wn + n8 * 8 + (lane & 3) * 2 + (e & 1);
                float v = acc[mi][n8][e] + bias[c];
                size_t off = (size_t)r * N + c;
                if (EPI == 0) {
                    Cf[off] = v;
                } else if (EPI == 1) {
                    v = 0.5f * v * (1.f + erff(v * 0.7071067811865475f));
                    split_bf16(v, Chi + off, Clo + off);
                } else {
                    Cf[off] = v + res[off];
                }
            }
        }
    }
}

// ---------------- Flash attention (causal, fp32) ----------------
__global__ __launch_bounds__(128) void attn_kernel(
    const float* __restrict__ qkv, bf16* __restrict__ outh, bf16* __restrict__ outl)
{
    __shared__ float4 Ks[64][16];
    __shared__ float4 Vs[64][16];

    int b = blockIdx.z;
    int h = blockIdx.y;
    int qi = blockIdx.x * 128 + threadIdx.x;

    const float* base = qkv + (size_t)b * SEQ * QKVDIM;
    const float* qrow = base + (size_t)qi * QKVDIM + h * HDIM;
    const float scale = 0.125f;

    float q[HDIM];
    for (int d = 0; d < HDIM; d += 4) {
        float4 t = *(const float4*)(qrow + d);
        q[d] = t.x * scale;
        q[d + 1] = t.y * scale;
        q[d + 2] = t.z * scale;
        q[d + 3] = t.w * scale;
    }

    float acc[HDIM];
    for (int d = 0; d < HDIM; d++) acc[d] = 0.f;
    float m = -1e30f;
    float l = 0.f;

    int ntiles = blockIdx.x * 2 + 2;
    int jr = threadIdx.x >> 1;
    int c0 = (threadIdx.x & 1) * 8;

    for (int kt = 0; kt < ntiles; kt++) {
        __syncthreads();
        const float* krow = base + (size_t)(kt * 64 + jr) * QKVDIM + CDIM + h * HDIM + c0 * 4;
        const float* vrow = krow + CDIM;
        for (int c = 0; c < 8; c++) {
            Ks[jr][c0 + c] = ((const float4*)krow)[c];
            Vs[jr][c0 + c] = ((const float4*)vrow)[c];
        }
        __syncthreads();

        int jmax = qi - kt * 64 + 1;
        if (jmax > 64) jmax = 64;
        for (int j = 0; j < jmax; j++) {
            float s0 = 0.f, s1 = 0.f, s2 = 0.f, s3 = 0.f;
            for (int d4 = 0; d4 < 16; d4++) {
                float4 kk = Ks[j][d4];
                s0 += q[d4 * 4    ] * kk.x;
                s1 += q[d4 * 4 + 1] * kk.y;
                s2 += q[d4 * 4 + 2] * kk.z;
                s3 += q[d4 * 4 + 3] * kk.w;
            }
            float s = (s0 + s1) + (s2 + s3);
            if (s <= m) {
                float p = __expf(s - m);
                l += p;
                for (int d4 = 0; d4 < 16; d4++) {
                    float4 vv = Vs[j][d4];
                    acc[d4 * 4    ] += p * vv.x;
                    acc[d4 * 4 + 1] += p * vv.y;
                    acc[d4 * 4 + 2] += p * vv.z;
                    acc[d4 * 4 + 3] += p * vv.w;
                }
            } else {
                float corr = __expf(m - s);
                m = s;
                l = l * corr + 1.f;
                for (int d4 = 0; d4 < 16; d4++) {
                    float4 vv = Vs[j][d4];
                    acc[d4 * 4    ] = acc[d4 * 4    ] * corr + vv.x;
                    acc[d4 * 4 + 1] = acc[d4 * 4 + 1] * corr + vv.y;
                    acc[d4 * 4 + 2] = acc[d4 * 4 + 2] * corr + vv.z;
                    acc[d4 * 4 + 3] = acc[d4 * 4 + 3] * corr + vv.w;
                }
            }
        }
    }

    float inv = 1.f / l;
    size_t obase = ((size_t)(b * SEQ + qi)) * CDIM + h * HDIM;
    for (int d = 0; d < HDIM; d++) {
        split_bf16(acc[d] * inv, outh + obase + d, outl + obase + d);
    }
}

// ---------------- launch ----------------
extern "C" void kernel_launch(void* const* d_in, const int* in_sizes, int n_in,
                              void* d_out, int out_size)
{
    const float* x           = (const float*)d_in[0];
    const float* ln1_w       = (const float*)d_in[1];
    const float* ln1_b       = (const float*)d_in[2];
    const float* W_attn      = (const float*)d_in[3];
    const float* b_attn      = (const float*)d_in[4];
    const float* W_attn_proj = (const float*)d_in[5];
    const float* b_attn_proj = (const float*)d_in[6];
    const float* ln2_w       = (const float*)d_in[7];
    const float* ln2_b       = (const float*)d_in[8];
    const float* W_fc        = (const float*)d_in[9];
    const float* b_fc        = (const float*)d_in[10];
    const float* W_mlp_proj  = (const float*)d_in[11];
    const float* b_mlp_proj  = (const float*)d_in[12];
    float* out = (float*)d_out;

    bf16 *p_lnh, *p_lnl, *p_atth, *p_attl, *p_fch, *p_fcl;
    bf16 *p_wah, *p_wal, *p_wph, *p_wpl, *p_wfh, *p_wfl, *p_wmh, *p_wml;
    float *p_qkv, *p_x1;
    cudaGetSymbolAddress((void**)&p_lnh,  g_lnh);
    cudaGetSymbolAddress((void**)&p_lnl,  g_lnl);
    cudaGetSymbolAddress((void**)&p_qkv,  g_qkv);
    cudaGetSymbolAddress((void**)&p_atth, g_atth);
    cudaGetSymbolAddress((void**)&p_attl, g_attl);
    cudaGetSymbolAddress((void**)&p_x1,   g_x1);
    cudaGetSymbolAddress((void**)&p_fch,  g_fch);
    cudaGetSymbolAddress((void**)&p_fcl,  g_fcl);
    cudaGetSymbolAddress((void**)&p_wah,  g_wah);
    cudaGetSymbolAddress((void**)&p_wal,  g_wal);
    cudaGetSymbolAddress((void**)&p_wph,  g_wph);
    cudaGetSymbolAddress((void**)&p_wpl,  g_wpl);
    cudaGetSymbolAddress((void**)&p_wfh,  g_wfh);
    cudaGetSymbolAddress((void**)&p_wfl,  g_wfl);
    cudaGetSymbolAddress((void**)&p_wmh,  g_wmh);
    cudaGetSymbolAddress((void**)&p_wml,  g_wml);

    cvt_kernel<<<(CDIM * QKVDIM + 255) / 256, 256>>>(W_attn,      p_wah, p_wal, CDIM * QKVDIM);
    cvt_kernel<<<(CDIM * CDIM   + 255) / 256, 256>>>(W_attn_proj, p_wph, p_wpl, CDIM * CDIM);
    cvt_kernel<<<(CDIM * FCDIM  + 255) / 256, 256>>>(W_fc,        p_wfh, p_wfl, CDIM * FCDIM);
    cvt_kernel<<<(FCDIM * CDIM  + 255) / 256, 256>>>(W_mlp_proj,  p_wmh, p_wml, FCDIM * CDIM);

    ln_kernel<<<MROWS, 256>>>(x, ln1_w, ln1_b, p_lnh, p_lnl);

    hgemm<0><<<dim3(QKVDIM / 128, MROWS / 128), 256>>>(p_lnh, p_lnl, p_wah, p_wal,
        b_attn, (const float*)0, p_qkv, (bf16*)0, (bf16*)0, MROWS, QKVDIM, CDIM);

    attn_kernel<<<dim3(SEQ / 128, NHEAD, BATCH), 128>>>(p_qkv, p_atth, p_attl);

    hgemm<2><<<dim3(CDIM / 128, MROWS / 128), 256>>>(p_atth, p_attl, p_wph, p_wpl,
        b_attn_proj, x, p_x1, (bf16*)0, (bf16*)0, MROWS, CDIM, CDIM);

    ln_kernel<<<MROWS, 256>>>(p_x1, ln2_w, ln2_b, p_lnh, p_lnl);

    hgemm<1><<<dim3(FCDIM / 128, MROWS / 128), 256>>>(p_lnh, p_lnl, p_wfh, p_wfl,
        b_fc, (const float*)0, (float*)0, p_fch, p_fcl, MROWS, FCDIM, CDIM);

    hgemm<2><<<dim3(CDIM / 128, MROWS / 128), 256>>>(p_fch, p_fcl, p_wmh, p_wml,
        b_mlp_proj, p_x1, out, (bf16*)0, (bf16*)0, MROWS, CDIM, FCDIM);
}

// round 5
// speedup vs baseline: 2.5637x; 1.7269x over previous
#include <cuda_runtime.h>
#include <cuda_bf16.h>
#include <stdint.h>
#include <math.h>

#define BATCH 4
#define SEQ   2048
#define CDIM  768
#define NHEAD 12
#define HDIM  64
#define MROWS 8192
#define QKVDIM 2304
#define FCDIM  3072

typedef __nv_bfloat16 bf16;

// ---------------- device scratch ----------------
__device__ bf16  g_lnh[MROWS*CDIM];
__device__ bf16  g_lnl[MROWS*CDIM];
__device__ bf16  g_qkvh[MROWS*QKVDIM];
__device__ bf16  g_qkvl[MROWS*QKVDIM];
__device__ bf16  g_atth[MROWS*CDIM];
__device__ bf16  g_attl[MROWS*CDIM];
__device__ float g_x1[MROWS*CDIM];
__device__ bf16  g_fch[MROWS*FCDIM];
__device__ bf16  g_fcl[MROWS*FCDIM];
__device__ bf16  g_wah[CDIM*QKVDIM];
__device__ bf16  g_wal[CDIM*QKVDIM];
__device__ bf16  g_wph[CDIM*CDIM];
__device__ bf16  g_wpl[CDIM*CDIM];
__device__ bf16  g_wfh[CDIM*FCDIM];
__device__ bf16  g_wfl[CDIM*FCDIM];
__device__ bf16  g_wmh[FCDIM*CDIM];
__device__ bf16  g_wml[FCDIM*CDIM];

__device__ __forceinline__ void split_bf16(float x, bf16* h, bf16* l)
{
    float hf = __bfloat162float(__float2bfloat16(x));
    *h = __float2bfloat16(x);
    *l = __float2bfloat16(x - hf);
}

__device__ __forceinline__ uint32_t packb(float x, float y)
{
    __nv_bfloat162 t = __floats2bfloat162_rn(x, y);
    return *(uint32_t*)&t;
}

// ---------------- fp32 -> hi/lo conversion ----------------
__global__ void cvt_kernel(const float* __restrict__ src, bf16* __restrict__ hi,
                           bf16* __restrict__ lo, int n)
{
    int i = blockIdx.x * 256 + threadIdx.x;
    if (i < n) {
        split_bf16(src[i], hi + i, lo + i);
    }
}

// ---------------- LayerNorm ----------------
__global__ __launch_bounds__(256) void ln_kernel(
    const float* __restrict__ x, const float* __restrict__ gw,
    const float* __restrict__ gb, bf16* __restrict__ oh, bf16* __restrict__ ol)
{
    __shared__ float ss[8];
    __shared__ float ss2[8];
    int row = blockIdx.x;
    const float* xr = x + (size_t)row * CDIM;
    float s = 0.f, s2 = 0.f;
    for (int i = threadIdx.x; i < CDIM; i += 256) {
        float t = xr[i];
        s += t;
        s2 += t * t;
    }
    for (int o = 16; o > 0; o >>= 1) {
        s  += __shfl_xor_sync(0xFFFFFFFFu, s,  o);
        s2 += __shfl_xor_sync(0xFFFFFFFFu, s2, o);
    }
    int wid = threadIdx.x >> 5;
    int lane = threadIdx.x & 31;
    if (lane == 0) {
        ss[wid] = s;
        ss2[wid] = s2;
    }
    __syncthreads();
    if (threadIdx.x == 0) {
        float a = 0.f, a2 = 0.f;
        for (int i = 0; i < 8; i++) {
            a += ss[i];
            a2 += ss2[i];
        }
        ss[0] = a;
        ss2[0] = a2;
    }
    __syncthreads();
    float mean = ss[0] * (1.f / CDIM);
    float var  = ss2[0] * (1.f / CDIM) - mean * mean;
    if (var < 0.f) var = 0.f;
    float inv = 1.f / (sqrtf(var) + 1e-6f);
    for (int i = threadIdx.x; i < CDIM; i += 256) {
        float v = gw[i] * (xr[i] - mean) * inv + gb[i];
        split_bf16(v, oh + (size_t)row * CDIM + i, ol + (size_t)row * CDIM + i);
    }
}

// ---------------- mma helpers (asm operand lists spaced) ----------------
__device__ __forceinline__ void ldsm_x4(uint32_t* r, const void* p)
{
    uint32_t addr = (uint32_t)__cvta_generic_to_shared(p);
    asm volatile("ldmatrix.sync.aligned.m8n8.x4.shared.b16 { %0, %1, %2, %3 }, [ %4 ];"
        : "=r"(r[0]), "=r"(r[1]), "=r"(r[2]), "=r"(r[3]) : "r"(addr));
}

__device__ __forceinline__ void ldsm_x4_t(uint32_t* r, const void* p)
{
    uint32_t addr = (uint32_t)__cvta_generic_to_shared(p);
    asm volatile("ldmatrix.sync.aligned.m8n8.x4.trans.shared.b16 { %0, %1, %2, %3 }, [ %4 ];"
        : "=r"(r[0]), "=r"(r[1]), "=r"(r[2]), "=r"(r[3]) : "r"(addr));
}

__device__ __forceinline__ void mma_bf16(float* c, const uint32_t* a,
                                         uint32_t b0, uint32_t b1)
{
    asm volatile("mma.sync.aligned.m16n8k16.row.col.f32.bf16.bf16.f32 "
        "{ %0, %1, %2, %3 }, { %4, %5, %6, %7 }, { %8, %9 }, { %0, %1, %2, %3 };"
        : "+f"(c[0]), "+f"(c[1]), "+f"(c[2]), "+f"(c[3])
        : "r"(a[0]), "r"(a[1]), "r"(a[2]), "r"(a[3]), "r"(b0), "r"(b1));
}

// ---------------- split-bf16 tensor-core GEMM ----------------
// EPI: 0 = bias -> fp32
//      1 = bias + GELU -> bf16 hi/lo
//      2 = bias + residual -> fp32
//      3 = bias -> bf16 hi/lo
template<int EPI>
__global__ __launch_bounds__(256, 2) void hgemm(
    const bf16* __restrict__ Ahi, const bf16* __restrict__ Alo,
    const bf16* __restrict__ Bhi, const bf16* __restrict__ Blo,
    const float* __restrict__ bias, const float* __restrict__ res,
    float* __restrict__ Cf, bf16* __restrict__ Chi, bf16* __restrict__ Clo,
    int M, int N, int K)
{
    __shared__ bf16 As[128][40];
    __shared__ bf16 Bs[32][136];

    const int tid  = threadIdx.x;
    const int lane = tid & 31;
    const int warp = tid >> 5;
    const int wm = (warp >> 1) * 32;
    const int wn = (warp & 1) * 64;
    const int row0 = blockIdx.y * 128;
    const int col0 = blockIdx.x * 128;

    const int rA0 = tid >> 2;
    const int cA0 = (tid & 3) * 8;
    const int rA1 = rA0 + 64;
    const int rB0 = tid >> 4;
    const int cB0 = (tid & 15) * 8;
    const int rB1 = rB0 + 16;

    const int KT = K / 32;
    const int NT = 3 * KT;

    float acc[2][8][4];
    #pragma unroll
    for (int i = 0; i < 2; i++) {
        #pragma unroll
        for (int j = 0; j < 8; j++) {
            #pragma unroll
            for (int e = 0; e < 4; e++) {
                acc[i][j][e] = 0.f;
            }
        }
    }

    uint4 ra0, ra1, rb0, rb1;

    ra0 = *(const uint4*)(Ahi + (size_t)(row0 + rA0) * K + cA0);
    ra1 = *(const uint4*)(Ahi + (size_t)(row0 + rA1) * K + cA0);
    rb0 = *(const uint4*)(Bhi + (size_t)rB0 * N + col0 + cB0);
    rb1 = *(const uint4*)(Bhi + (size_t)rB1 * N + col0 + cB0);

    for (int it = 0; it < NT; ++it) {
        *(uint4*)&As[rA0][cA0] = ra0;
        *(uint4*)&As[rA1][cA0] = ra1;
        *(uint4*)&Bs[rB0][cB0] = rb0;
        *(uint4*)&Bs[rB1][cB0] = rb1;
        __syncthreads();

        if (it + 1 < NT) {
            int nit = it + 1;
            int ph = nit / KT;
            int kk = (nit % KT) * 32;
            const bf16* Ap = (ph == 1) ? Alo : Ahi;
            const bf16* Bp = (ph == 2) ? Blo : Bhi;
            ra0 = *(const uint4*)(Ap + (size_t)(row0 + rA0) * K + kk + cA0);
            ra1 = *(const uint4*)(Ap + (size_t)(row0 + rA1) * K + kk + cA0);
            rb0 = *(const uint4*)(Bp + (size_t)(kk + rB0) * N + col0 + cB0);
            rb1 = *(const uint4*)(Bp + (size_t)(kk + rB1) * N + col0 + cB0);
        }

        #pragma unroll
        for (int ks = 0; ks < 2; ++ks) {
            const int k0 = ks * 16;
            uint32_t af0[4];
            uint32_t af1[4];
            ldsm_x4(af0, &As[wm + (lane & 15)][k0 + (lane >> 4) * 8]);
            ldsm_x4(af1, &As[wm + 16 + (lane & 15)][k0 + (lane >> 4) * 8]);
            #pragma unroll
            for (int ni = 0; ni < 4; ++ni) {
                uint32_t bb[4];
                ldsm_x4_t(bb, &Bs[k0 + (lane & 15)][wn + ni * 16 + (lane >> 4) * 8]);
                mma_bf16(acc[0][ni * 2 + 0], af0, bb[0], bb[1]);
                mma_bf16(acc[0][ni * 2 + 1], af0, bb[2], bb[3]);
                mma_bf16(acc[1][ni * 2 + 0], af1, bb[0], bb[1]);
                mma_bf16(acc[1][ni * 2 + 1], af1, bb[2], bb[3]);
            }
        }
        __syncthreads();
    }

    #pragma unroll
    for (int mi = 0; mi < 2; ++mi) {
        #pragma unroll
        for (int n8 = 0; n8 < 8; ++n8) {
            #pragma unroll
            for (int e = 0; e < 4; ++e) {
                int r = row0 + wm + mi * 16 + (lane >> 2) + (e >> 1) * 8;
                int c = col0 + wn + n8 * 8 + (lane & 3) * 2 + (e & 1);
                float v = acc[mi][n8][e] + bias[c];
                size_t off = (size_t)r * N + c;
                if (EPI == 0) {
                    Cf[off] = v;
                } else if (EPI == 1) {
                    v = 0.5f * v * (1.f + erff(v * 0.7071067811865475f));
                    split_bf16(v, Chi + off, Clo + off);
                } else if (EPI == 3) {
                    split_bf16(v, Chi + off, Clo + off);
                } else {
                    Cf[off] = v + res[off];
                }
            }
        }
    }
}

// ---------------- Tensor-core flash attention (causal) ----------------
// grid: (SEQ/64, NHEAD, BATCH), 128 threads = 4 warps; warp owns 16 query rows.
// Scores via 3-phase hi/lo bf16 mma (fp32-accurate); P*V in bf16.
__global__ __launch_bounds__(128) void fattn_kernel(
    const bf16* __restrict__ qkvh, const bf16* __restrict__ qkvl,
    bf16* __restrict__ outh, bf16* __restrict__ outl)
{
    __shared__ bf16 Qs[64][72];
    __shared__ bf16 KsH[64][72];
    __shared__ bf16 KsL[64][72];
    __shared__ bf16 Vs[64][72];

    const int b = blockIdx.z;
    const int h = blockIdx.y;
    const int qb = blockIdx.x;
    const int tid = threadIdx.x;
    const int lane = tid & 31;
    const int warp = tid >> 5;
    const int row0 = qb * 64;

    const size_t base = (size_t)b * SEQ * QKVDIM;

    // ---- stage Q (hi), extract frags, then lo ----
    #pragma unroll
    for (int i = 0; i < 4; i++) {
        int e = tid + i * 128;
        int r = e >> 3;
        int c = (e & 7) * 8;
        *(uint4*)&Qs[r][c] = *(const uint4*)(qkvh + base + (size_t)(row0 + r) * QKVDIM + h * HDIM + c);
    }
    __syncthreads();
    uint32_t qh[4][4];
    uint32_t ql[4][4];
    #pragma unroll
    for (int kf = 0; kf < 4; kf++) {
        ldsm_x4(qh[kf], &Qs[warp * 16 + (lane & 15)][kf * 16 + (lane >> 4) * 8]);
    }
    __syncthreads();
    #pragma unroll
    for (int i = 0; i < 4; i++) {
        int e = tid + i * 128;
        int r = e >> 3;
        int c = (e & 7) * 8;
        *(uint4*)&Qs[r][c] = *(const uint4*)(qkvl + base + (size_t)(row0 + r) * QKVDIM + h * HDIM + c);
    }
    __syncthreads();
    #pragma unroll
    for (int kf = 0; kf < 4; kf++) {
        ldsm_x4(ql[kf], &Qs[warp * 16 + (lane & 15)][kf * 16 + (lane >> 4) * 8]);
    }

    float oacc[8][4];
    #pragma unroll
    for (int nb = 0; nb < 8; nb++) {
        #pragma unroll
        for (int e = 0; e < 4; e++) {
            oacc[nb][e] = 0.f;
        }
    }
    float m1 = -1e30f, m2 = -1e30f;
    float l1 = 0.f, l2 = 0.f;

    const int r1g = row0 + warp * 16 + (lane >> 2);
    const int r2g = r1g + 8;
    const float SC = 0.125f;

    for (int kt = 0; kt <= qb; kt++) {
        const int j0g = kt * 64;
        __syncthreads();
        #pragma unroll
        for (int i = 0; i < 4; i++) {
            int e = tid + i * 128;
            int r = e >> 3;
            int c = (e & 7) * 8;
            size_t goff = base + (size_t)(j0g + r) * QKVDIM + CDIM + h * HDIM + c;
            *(uint4*)&KsH[r][c] = *(const uint4*)(qkvh + goff);
            *(uint4*)&KsL[r][c] = *(const uint4*)(qkvl + goff);
            *(uint4*)&Vs[r][c]  = *(const uint4*)(qkvh + goff + CDIM);
        }
        __syncthreads();

        // ---- S = Q K^T (3 phases) ----
        float sacc[8][4];
        #pragma unroll
        for (int nb = 0; nb < 8; nb++) {
            #pragma unroll
            for (int e = 0; e < 4; e++) {
                sacc[nb][e] = 0.f;
            }
        }
        #pragma unroll
        for (int kf = 0; kf < 4; kf++) {
            const int d0 = kf * 16;
            #pragma unroll
            for (int p = 0; p < 4; p++) {
                const int j0 = p * 16;
                uint32_t bh[4];
                uint32_t bl[4];
                // non-trans ldmatrix, B-operand pattern (col-major B == row-major [n][k])
                ldsm_x4(bh, &KsH[j0 + ((lane >> 4) << 3) + (lane & 7)][d0 + (((lane >> 3) & 1) << 3)]);
                mma_bf16(sacc[p * 2 + 0], qh[kf], bh[0], bh[1]);
                mma_bf16(sacc[p * 2 + 1], qh[kf], bh[2], bh[3]);
                mma_bf16(sacc[p * 2 + 0], ql[kf], bh[0], bh[1]);
                mma_bf16(sacc[p * 2 + 1], ql[kf], bh[2], bh[3]);
                ldsm_x4(bl, &KsL[j0 + ((lane >> 4) << 3) + (lane & 7)][d0 + (((lane >> 3) & 1) << 3)]);
                mma_bf16(sacc[p * 2 + 0], qh[kf], bl[0], bl[1]);
                mma_bf16(sacc[p * 2 + 1], qh[kf], bl[2], bl[3]);
            }
        }

        // ---- scale + causal mask ----
        if (kt == qb) {
            #pragma unroll
            for (int nb = 0; nb < 8; nb++) {
                int jg = j0g + nb * 8 + (lane & 3) * 2;
                sacc[nb][0] = (jg     <= r1g) ? sacc[nb][0] * SC : -1e30f;
                sacc[nb][1] = (jg + 1 <= r1g) ? sacc[nb][1] * SC : -1e30f;
                sacc[nb][2] = (jg     <= r2g) ? sacc[nb][2] * SC : -1e30f;
                sacc[nb][3] = (jg + 1 <= r2g) ? sacc[nb][3] * SC : -1e30f;
            }
        } else {
            #pragma unroll
            for (int nb = 0; nb < 8; nb++) {
                #pragma unroll
                for (int e = 0; e < 4; e++) {
                    sacc[nb][e] *= SC;
                }
            }
        }

        // ---- online softmax ----
        float mx1 = -1e30f, mx2 = -1e30f;
        #pragma unroll
        for (int nb = 0; nb < 8; nb++) {
            mx1 = fmaxf(mx1, fmaxf(sacc[nb][0], sacc[nb][1]));
            mx2 = fmaxf(mx2, fmaxf(sacc[nb][2], sacc[nb][3]));
        }
        mx1 = fmaxf(mx1, __shfl_xor_sync(0xFFFFFFFFu, mx1, 1));
        mx1 = fmaxf(mx1, __shfl_xor_sync(0xFFFFFFFFu, mx1, 2));
        mx2 = fmaxf(mx2, __shfl_xor_sync(0xFFFFFFFFu, mx2, 1));
        mx2 = fmaxf(mx2, __shfl_xor_sync(0xFFFFFFFFu, mx2, 2));

        float nm1 = fmaxf(m1, mx1);
        float nm2 = fmaxf(m2, mx2);
        float co1 = __expf(m1 - nm1);
        float co2 = __expf(m2 - nm2);
        m1 = nm1;
        m2 = nm2;

        uint32_t pa1[8];
        uint32_t pa2[8];
        float ps1 = 0.f, ps2 = 0.f;
        #pragma unroll
        for (int nb = 0; nb < 8; nb++) {
            float p0 = __expf(sacc[nb][0] - m1);
            float p1 = __expf(sacc[nb][1] - m1);
            float p2 = __expf(sacc[nb][2] - m2);
            float p3 = __expf(sacc[nb][3] - m2);
            ps1 += p0 + p1;
            ps2 += p2 + p3;
            pa1[nb] = packb(p0, p1);
            pa2[nb] = packb(p2, p3);
        }
        l1 = l1 * co1 + ps1;
        l2 = l2 * co2 + ps2;
        #pragma unroll
        for (int nb = 0; nb < 8; nb++) {
            oacc[nb][0] *= co1;
            oacc[nb][1] *= co1;
            oacc[nb][2] *= co2;
            oacc[nb][3] *= co2;
        }

        // ---- O += P V ----
        #pragma unroll
        for (int kf = 0; kf < 4; kf++) {
            uint32_t af[4];
            af[0] = pa1[kf * 2];
            af[1] = pa2[kf * 2];
            af[2] = pa1[kf * 2 + 1];
            af[3] = pa2[kf * 2 + 1];
            #pragma unroll
            for (int pd = 0; pd < 4; pd++) {
                uint32_t bb[4];
                ldsm_x4_t(bb, &Vs[kf * 16 + (lane & 15)][pd * 16 + (lane >> 4) * 8]);
                mma_bf16(oacc[pd * 2 + 0], af, bb[0], bb[1]);
                mma_bf16(oacc[pd * 2 + 1], af, bb[2], bb[3]);
            }
        }
    }

    // ---- finalize ----
    l1 += __shfl_xor_sync(0xFFFFFFFFu, l1, 1);
    l1 += __shfl_xor_sync(0xFFFFFFFFu, l1, 2);
    l2 += __shfl_xor_sync(0xFFFFFFFFu, l2, 1);
    l2 += __shfl_xor_sync(0xFFFFFFFFu, l2, 2);
    float inv1 = 1.f / l1;
    float inv2 = 1.f / l2;

    size_t ob1 = (size_t)(b * SEQ + r1g) * CDIM + h * HDIM;
    size_t ob2 = (size_t)(b * SEQ + r2g) * CDIM + h * HDIM;
    #pragma unroll
    for (int nb = 0; nb < 8; nb++) {
        int c = nb * 8 + (lane & 3) * 2;
        split_bf16(oacc[nb][0] * inv1, outh + ob1 + c,     outl + ob1 + c);
        split_bf16(oacc[nb][1] * inv1, outh + ob1 + c + 1, outl + ob1 + c + 1);
        split_bf16(oacc[nb][2] * inv2, outh + ob2 + c,     outl + ob2 + c);
        split_bf16(oacc[nb][3] * inv2, outh + ob2 + c + 1, outl + ob2 + c + 1);
    }
}

// ---------------- launch ----------------
extern "C" void kernel_launch(void* const* d_in, const int* in_sizes, int n_in,
                              void* d_out, int out_size)
{
    const float* x           = (const float*)d_in[0];
    const float* ln1_w       = (const float*)d_in[1];
    const float* ln1_b       = (const float*)d_in[2];
    const float* W_attn      = (const float*)d_in[3];
    const float* b_attn      = (const float*)d_in[4];
    const float* W_attn_proj = (const float*)d_in[5];
    const float* b_attn_proj = (const float*)d_in[6];
    const float* ln2_w       = (const float*)d_in[7];
    const float* ln2_b       = (const float*)d_in[8];
    const float* W_fc        = (const float*)d_in[9];
    const float* b_fc        = (const float*)d_in[10];
    const float* W_mlp_proj  = (const float*)d_in[11];
    const float* b_mlp_proj  = (const float*)d_in[12];
    float* out = (float*)d_out;

    bf16 *p_lnh, *p_lnl, *p_qkvh, *p_qkvl, *p_atth, *p_attl, *p_fch, *p_fcl;
    bf16 *p_wah, *p_wal, *p_wph, *p_wpl, *p_wfh, *p_wfl, *p_wmh, *p_wml;
    float *p_x1;
    cudaGetSymbolAddress((void**)&p_lnh,  g_lnh);
    cudaGetSymbolAddress((void**)&p_lnl,  g_lnl);
    cudaGetSymbolAddress((void**)&p_qkvh, g_qkvh);
    cudaGetSymbolAddress((void**)&p_qkvl, g_qkvl);
    cudaGetSymbolAddress((void**)&p_atth, g_atth);
    cudaGetSymbolAddress((void**)&p_attl, g_attl);
    cudaGetSymbolAddress((void**)&p_x1,   g_x1);
    cudaGetSymbolAddress((void**)&p_fch,  g_fch);
    cudaGetSymbolAddress((void**)&p_fcl,  g_fcl);
    cudaGetSymbolAddress((void**)&p_wah,  g_wah);
    cudaGetSymbolAddress((void**)&p_wal,  g_wal);
    cudaGetSymbolAddress((void**)&p_wph,  g_wph);
    cudaGetSymbolAddress((void**)&p_wpl,  g_wpl);
    cudaGetSymbolAddress((void**)&p_wfh,  g_wfh);
    cudaGetSymbolAddress((void**)&p_wfl,  g_wfl);
    cudaGetSymbolAddress((void**)&p_wmh,  g_wmh);
    cudaGetSymbolAddress((void**)&p_wml,  g_wml);

    cvt_kernel<<<(CDIM * QKVDIM + 255) / 256, 256>>>(W_attn,      p_wah, p_wal, CDIM * QKVDIM);
    cvt_kernel<<<(CDIM * CDIM   + 255) / 256, 256>>>(W_attn_proj, p_wph, p_wpl, CDIM * CDIM);
    cvt_kernel<<<(CDIM * FCDIM  + 255) / 256, 256>>>(W_fc,        p_wfh, p_wfl, CDIM * FCDIM);
    cvt_kernel<<<(FCDIM * CDIM  + 255) / 256, 256>>>(W_mlp_proj,  p_wmh, p_wml, FCDIM * CDIM);

    ln_kernel<<<MROWS, 256>>>(x, ln1_w, ln1_b, p_lnh, p_lnl);

    hgemm<3><<<dim3(QKVDIM / 128, MROWS / 128), 256>>>(p_lnh, p_lnl, p_wah, p_wal,
        b_attn, (const float*)0, (float*)0, p_qkvh, p_qkvl, MROWS, QKVDIM, CDIM);

    fattn_kernel<<<dim3(SEQ / 64, NHEAD, BATCH), 128>>>(p_qkvh, p_qkvl, p_atth, p_attl);

    hgemm<2><<<dim3(CDIM / 128, MROWS / 128), 256>>>(p_atth, p_attl, p_wph, p_wpl,
        b_attn_proj, x, p_x1, (bf16*)0, (bf16*)0, MROWS, CDIM, CDIM);

    ln_kernel<<<MROWS, 256>>>(p_x1, ln2_w, ln2_b, p_lnh, p_lnl);

    hgemm<1><<<dim3(FCDIM / 128, MROWS / 128), 256>>>(p_lnh, p_lnl, p_wfh, p_wfl,
        b_fc, (const float*)0, (float*)0, p_fch, p_fcl, MROWS, FCDIM, CDIM);

    hgemm<2><<<dim3(CDIM / 128, MROWS / 128), 256>>>(p_fch, p_fcl, p_wmh, p_wml,
        b_mlp_proj, p_x1, out, (bf16*)0, (bf16*)0, MROWS, CDIM, FCDIM);
}

// round 6
// speedup vs baseline: 3.4280x; 1.3371x over previous
#include <cuda_runtime.h>
#include <cuda_bf16.h>
#include <stdint.h>
#include <math.h>

#define BATCH 4
#define SEQ   2048
#define CDIM  768
#define NHEAD 12
#define HDIM  64
#define MROWS 8192
#define QKVDIM 2304
#define FCDIM  3072

typedef __nv_bfloat16 bf16;

// ---------------- device scratch ----------------
__device__ bf16  g_lnh[MROWS*CDIM];
__device__ bf16  g_lnl[MROWS*CDIM];
__device__ bf16  g_qkvh[MROWS*QKVDIM];
__device__ bf16  g_qkvl[MROWS*QKVDIM];
__device__ bf16  g_atth[MROWS*CDIM];
__device__ bf16  g_attl[MROWS*CDIM];
__device__ float g_x1[MROWS*CDIM];
__device__ bf16  g_fch[MROWS*FCDIM];
__device__ bf16  g_fcl[MROWS*FCDIM];
__device__ bf16  g_wah[CDIM*QKVDIM];
__device__ bf16  g_wph[CDIM*CDIM];
__device__ bf16  g_wfh[CDIM*FCDIM];
__device__ bf16  g_wmh[FCDIM*CDIM];

__device__ __forceinline__ void split_bf16(float x, bf16* h, bf16* l)
{
    float hf = __bfloat162float(__float2bfloat16(x));
    *h = __float2bfloat16(x);
    *l = __float2bfloat16(x - hf);
}

__device__ __forceinline__ uint32_t packb(float x, float y)
{
    __nv_bfloat162 t = __floats2bfloat162_rn(x, y);
    return *(uint32_t*)&t;
}

// ---------------- fp32 -> bf16 weight conversion (hi plane only) ----------------
__global__ void cvt_kernel(const float* __restrict__ src, bf16* __restrict__ hi, int n)
{
    int i = blockIdx.x * 256 + threadIdx.x;
    if (i < n) {
        hi[i] = __float2bfloat16(src[i]);
    }
}

// ---------------- LayerNorm ----------------
__global__ __launch_bounds__(256) void ln_kernel(
    const float* __restrict__ x, const float* __restrict__ gw,
    const float* __restrict__ gb, bf16* __restrict__ oh, bf16* __restrict__ ol)
{
    __shared__ float ss[8];
    __shared__ float ss2[8];
    int row = blockIdx.x;
    const float* xr = x + (size_t)row * CDIM;
    float s = 0.f, s2 = 0.f;
    for (int i = threadIdx.x; i < CDIM; i += 256) {
        float t = xr[i];
        s += t;
        s2 += t * t;
    }
    for (int o = 16; o > 0; o >>= 1) {
        s  += __shfl_xor_sync(0xFFFFFFFFu, s,  o);
        s2 += __shfl_xor_sync(0xFFFFFFFFu, s2, o);
    }
    int wid = threadIdx.x >> 5;
    int lane = threadIdx.x & 31;
    if (lane == 0) {
        ss[wid] = s;
        ss2[wid] = s2;
    }
    __syncthreads();
    if (threadIdx.x == 0) {
        float a = 0.f, a2 = 0.f;
        for (int i = 0; i < 8; i++) {
            a += ss[i];
            a2 += ss2[i];
        }
        ss[0] = a;
        ss2[0] = a2;
    }
    __syncthreads();
    float mean = ss[0] * (1.f / CDIM);
    float var  = ss2[0] * (1.f / CDIM) - mean * mean;
    if (var < 0.f) var = 0.f;
    float inv = 1.f / (sqrtf(var) + 1e-6f);
    for (int i = threadIdx.x; i < CDIM; i += 256) {
        float v = gw[i] * (xr[i] - mean) * inv + gb[i];
        split_bf16(v, oh + (size_t)row * CDIM + i, ol + (size_t)row * CDIM + i);
    }
}

// ---------------- mma helpers (asm operand lists spaced) ----------------
__device__ __forceinline__ void ldsm_x4(uint32_t* r, const void* p)
{
    uint32_t addr = (uint32_t)__cvta_generic_to_shared(p);
    asm volatile("ldmatrix.sync.aligned.m8n8.x4.shared.b16 { %0, %1, %2, %3 }, [ %4 ];"
        : "=r"(r[0]), "=r"(r[1]), "=r"(r[2]), "=r"(r[3]) : "r"(addr));
}

__device__ __forceinline__ void ldsm_x4_t(uint32_t* r, const void* p)
{
    uint32_t addr = (uint32_t)__cvta_generic_to_shared(p);
    asm volatile("ldmatrix.sync.aligned.m8n8.x4.trans.shared.b16 { %0, %1, %2, %3 }, [ %4 ];"
        : "=r"(r[0]), "=r"(r[1]), "=r"(r[2]), "=r"(r[3]) : "r"(addr));
}

__device__ __forceinline__ void mma_bf16(float* c, const uint32_t* a,
                                         uint32_t b0, uint32_t b1)
{
    asm volatile("mma.sync.aligned.m16n8k16.row.col.f32.bf16.bf16.f32 "
        "{ %0, %1, %2, %3 }, { %4, %5, %6, %7 }, { %8, %9 }, { %0, %1, %2, %3 };"
        : "+f"(c[0]), "+f"(c[1]), "+f"(c[2]), "+f"(c[3])
        : "r"(a[0]), "r"(a[1]), "r"(a[2]), "r"(a[3]), "r"(b0), "r"(b1));
}

// ---------------- 2-phase split-bf16 tensor-core GEMM ----------------
// C = (A_hi + A_lo) @ B_hi + bias (+epilogue). 2 K-phases, fp32 accumulate.
// EPI: 0 = bias -> fp32
//      1 = bias + GELU -> bf16 hi/lo
//      2 = bias + residual -> fp32
//      3 = bias -> bf16 hi/lo
template<int EPI>
__global__ __launch_bounds__(256, 2) void hgemm(
    const bf16* __restrict__ Ahi, const bf16* __restrict__ Alo,
    const bf16* __restrict__ Bhi,
    const float* __restrict__ bias, const float* __restrict__ res,
    float* __restrict__ Cf, bf16* __restrict__ Chi, bf16* __restrict__ Clo,
    int M, int N, int K)
{
    __shared__ bf16 As[128][40];
    __shared__ bf16 Bs[32][136];

    const int tid  = threadIdx.x;
    const int lane = tid & 31;
    const int warp = tid >> 5;
    const int wm = (warp >> 1) * 32;
    const int wn = (warp & 1) * 64;
    const int row0 = blockIdx.y * 128;
    const int col0 = blockIdx.x * 128;

    const int rA0 = tid >> 2;
    const int cA0 = (tid & 3) * 8;
    const int rA1 = rA0 + 64;
    const int rB0 = tid >> 4;
    const int cB0 = (tid & 15) * 8;
    const int rB1 = rB0 + 16;

    const int KT = K / 32;
    const int NT = 2 * KT;

    float acc[2][8][4];
    #pragma unroll
    for (int i = 0; i < 2; i++) {
        #pragma unroll
        for (int j = 0; j < 8; j++) {
            #pragma unroll
            for (int e = 0; e < 4; e++) {
                acc[i][j][e] = 0.f;
            }
        }
    }

    uint4 ra0, ra1, rb0, rb1;

    ra0 = *(const uint4*)(Ahi + (size_t)(row0 + rA0) * K + cA0);
    ra1 = *(const uint4*)(Ahi + (size_t)(row0 + rA1) * K + cA0);
    rb0 = *(const uint4*)(Bhi + (size_t)rB0 * N + col0 + cB0);
    rb1 = *(const uint4*)(Bhi + (size_t)rB1 * N + col0 + cB0);

    for (int it = 0; it < NT; ++it) {
        *(uint4*)&As[rA0][cA0] = ra0;
        *(uint4*)&As[rA1][cA0] = ra1;
        *(uint4*)&Bs[rB0][cB0] = rb0;
        *(uint4*)&Bs[rB1][cB0] = rb1;
        __syncthreads();

        if (it + 1 < NT) {
            int nit = it + 1;
            int ph = nit / KT;
            int kk = (nit % KT) * 32;
            const bf16* Ap = (ph == 1) ? Alo : Ahi;
            ra0 = *(const uint4*)(Ap + (size_t)(row0 + rA0) * K + kk + cA0);
            ra1 = *(const uint4*)(Ap + (size_t)(row0 + rA1) * K + kk + cA0);
            rb0 = *(const uint4*)(Bhi + (size_t)(kk + rB0) * N + col0 + cB0);
            rb1 = *(const uint4*)(Bhi + (size_t)(kk + rB1) * N + col0 + cB0);
        }

        #pragma unroll
        for (int ks = 0; ks < 2; ++ks) {
            const int k0 = ks * 16;
            uint32_t af0[4];
            uint32_t af1[4];
            ldsm_x4(af0, &As[wm + (lane & 15)][k0 + (lane >> 4) * 8]);
            ldsm_x4(af1, &As[wm + 16 + (lane & 15)][k0 + (lane >> 4) * 8]);
            #pragma unroll
            for (int ni = 0; ni < 4; ++ni) {
                uint32_t bb[4];
                ldsm_x4_t(bb, &Bs[k0 + (lane & 15)][wn + ni * 16 + (lane >> 4) * 8]);
                mma_bf16(acc[0][ni * 2 + 0], af0, bb[0], bb[1]);
                mma_bf16(acc[0][ni * 2 + 1], af0, bb[2], bb[3]);
                mma_bf16(acc[1][ni * 2 + 0], af1, bb[0], bb[1]);
                mma_bf16(acc[1][ni * 2 + 1], af1, bb[2], bb[3]);
            }
        }
        __syncthreads();
    }

    #pragma unroll
    for (int mi = 0; mi < 2; ++mi) {
        #pragma unroll
        for (int n8 = 0; n8 < 8; ++n8) {
            #pragma unroll
            for (int e = 0; e < 4; ++e) {
                int r = row0 + wm + mi * 16 + (lane >> 2) + (e >> 1) * 8;
                int c = col0 + wn + n8 * 8 + (lane & 3) * 2 + (e & 1);
                float v = acc[mi][n8][e] + bias[c];
                size_t off = (size_t)r * N + c;
                if (EPI == 0) {
                    Cf[off] = v;
                } else if (EPI == 1) {
                    v = 0.5f * v * (1.f + erff(v * 0.7071067811865475f));
                    split_bf16(v, Chi + off, Clo + off);
                } else if (EPI == 3) {
                    split_bf16(v, Chi + off, Clo + off);
                } else {
                    Cf[off] = v + res[off];
                }
            }
        }
    }
}

// ---------------- Tensor-core flash attention (causal) ----------------
// grid: (SEQ/64, NHEAD, BATCH), 128 threads = 4 warps; warp owns 16 query rows.
// Scores: 2-phase (q_hi + q_lo) . k_hi via mma; P*V in bf16.
__global__ __launch_bounds__(128) void fattn_kernel(
    const bf16* __restrict__ qkvh, const bf16* __restrict__ qkvl,
    bf16* __restrict__ outh, bf16* __restrict__ outl)
{
    __shared__ bf16 Qs[64][72];
    __shared__ bf16 KsH[64][72];
    __shared__ bf16 Vs[64][72];

    const int b = blockIdx.z;
    const int h = blockIdx.y;
    const int qb = blockIdx.x;
    const int tid = threadIdx.x;
    const int lane = tid & 31;
    const int warp = tid >> 5;
    const int row0 = qb * 64;

    const size_t base = (size_t)b * SEQ * QKVDIM;

    // ---- stage Q (hi), extract frags, then lo ----
    #pragma unroll
    for (int i = 0; i < 4; i++) {
        int e = tid + i * 128;
        int r = e >> 3;
        int c = (e & 7) * 8;
        *(uint4*)&Qs[r][c] = *(const uint4*)(qkvh + base + (size_t)(row0 + r) * QKVDIM + h * HDIM + c);
    }
    __syncthreads();
    uint32_t qh[4][4];
    uint32_t ql[4][4];
    #pragma unroll
    for (int kf = 0; kf < 4; kf++) {
        ldsm_x4(qh[kf], &Qs[warp * 16 + (lane & 15)][kf * 16 + (lane >> 4) * 8]);
    }
    __syncthreads();
    #pragma unroll
    for (int i = 0; i < 4; i++) {
        int e = tid + i * 128;
        int r = e >> 3;
        int c = (e & 7) * 8;
        *(uint4*)&Qs[r][c] = *(const uint4*)(qkvl + base + (size_t)(row0 + r) * QKVDIM + h * HDIM + c);
    }
    __syncthreads();
    #pragma unroll
    for (int kf = 0; kf < 4; kf++) {
        ldsm_x4(ql[kf], &Qs[warp * 16 + (lane & 15)][kf * 16 + (lane >> 4) * 8]);
    }

    float oacc[8][4];
    #pragma unroll
    for (int nb = 0; nb < 8; nb++) {
        #pragma unroll
        for (int e = 0; e < 4; e++) {
            oacc[nb][e] = 0.f;
        }
    }
    float m1 = -1e30f, m2 = -1e30f;
    float l1 = 0.f, l2 = 0.f;

    const int r1g = row0 + warp * 16 + (lane >> 2);
    const int r2g = r1g + 8;
    const float SC = 0.125f;

    for (int kt = 0; kt <= qb; kt++) {
        const int j0g = kt * 64;
        __syncthreads();
        #pragma unroll
        for (int i = 0; i < 4; i++) {
            int e = tid + i * 128;
            int r = e >> 3;
            int c = (e & 7) * 8;
            size_t goff = base + (size_t)(j0g + r) * QKVDIM + CDIM + h * HDIM + c;
            *(uint4*)&KsH[r][c] = *(const uint4*)(qkvh + goff);
            *(uint4*)&Vs[r][c]  = *(const uint4*)(qkvh + goff + CDIM);
        }
        __syncthreads();

        // ---- S = Q K^T (2 phases) ----
        float sacc[8][4];
        #pragma unroll
        for (int nb = 0; nb < 8; nb++) {
            #pragma unroll
            for (int e = 0; e < 4; e++) {
                sacc[nb][e] = 0.f;
            }
        }
        #pragma unroll
        for (int kf = 0; kf < 4; kf++) {
            const int d0 = kf * 16;
            #pragma unroll
            for (int p = 0; p < 4; p++) {
                const int j0 = p * 16;
                uint32_t bh[4];
                // non-trans ldmatrix, B-operand pattern (col-major B == row-major [n][k])
                ldsm_x4(bh, &KsH[j0 + ((lane >> 4) << 3) + (lane & 7)][d0 + (((lane >> 3) & 1) << 3)]);
                mma_bf16(sacc[p * 2 + 0], qh[kf], bh[0], bh[1]);
                mma_bf16(sacc[p * 2 + 1], qh[kf], bh[2], bh[3]);
                mma_bf16(sacc[p * 2 + 0], ql[kf], bh[0], bh[1]);
                mma_bf16(sacc[p * 2 + 1], ql[kf], bh[2], bh[3]);
            }
        }

        // ---- scale + causal mask ----
        if (kt == qb) {
            #pragma unroll
            for (int nb = 0; nb < 8; nb++) {
                int jg = j0g + nb * 8 + (lane & 3) * 2;
                sacc[nb][0] = (jg     <= r1g) ? sacc[nb][0] * SC : -1e30f;
                sacc[nb][1] = (jg + 1 <= r1g) ? sacc[nb][1] * SC : -1e30f;
                sacc[nb][2] = (jg     <= r2g) ? sacc[nb][2] * SC : -1e30f;
                sacc[nb][3] = (jg + 1 <= r2g) ? sacc[nb][3] * SC : -1e30f;
            }
        } else {
            #pragma unroll
            for (int nb = 0; nb < 8; nb++) {
                #pragma unroll
                for (int e = 0; e < 4; e++) {
                    sacc[nb][e] *= SC;
                }
            }
        }

        // ---- online softmax ----
        float mx1 = -1e30f, mx2 = -1e30f;
        #pragma unroll
        for (int nb = 0; nb < 8; nb++) {
            mx1 = fmaxf(mx1, fmaxf(sacc[nb][0], sacc[nb][1]));
            mx2 = fmaxf(mx2, fmaxf(sacc[nb][2], sacc[nb][3]));
        }
        mx1 = fmaxf(mx1, __shfl_xor_sync(0xFFFFFFFFu, mx1, 1));
        mx1 = fmaxf(mx1, __shfl_xor_sync(0xFFFFFFFFu, mx1, 2));
        mx2 = fmaxf(mx2, __shfl_xor_sync(0xFFFFFFFFu, mx2, 1));
        mx2 = fmaxf(mx2, __shfl_xor_sync(0xFFFFFFFFu, mx2, 2));

        float nm1 = fmaxf(m1, mx1);
        float nm2 = fmaxf(m2, mx2);
        float co1 = __expf(m1 - nm1);
        float co2 = __expf(m2 - nm2);
        m1 = nm1;
        m2 = nm2;

        uint32_t pa1[8];
        uint32_t pa2[8];
        float ps1 = 0.f, ps2 = 0.f;
        #pragma unroll
        for (int nb = 0; nb < 8; nb++) {
            float p0 = __expf(sacc[nb][0] - m1);
            float p1 = __expf(sacc[nb][1] - m1);
            float p2 = __expf(sacc[nb][2] - m2);
            float p3 = __expf(sacc[nb][3] - m2);
            ps1 += p0 + p1;
            ps2 += p2 + p3;
            pa1[nb] = packb(p0, p1);
            pa2[nb] = packb(p2, p3);
        }
        l1 = l1 * co1 + ps1;
        l2 = l2 * co2 + ps2;
        #pragma unroll
        for (int nb = 0; nb < 8; nb++) {
            oacc[nb][0] *= co1;
            oacc[nb][1] *= co1;
            oacc[nb][2] *= co2;
            oacc[nb][3] *= co2;
        }

        // ---- O += P V ----
        #pragma unroll
        for (int kf = 0; kf < 4; kf++) {
            uint32_t af[4];
            af[0] = pa1[kf * 2];
            af[1] = pa2[kf * 2];
            af[2] = pa1[kf * 2 + 1];
            af[3] = pa2[kf * 2 + 1];
            #pragma unroll
            for (int pd = 0; pd < 4; pd++) {
                uint32_t bb[4];
                ldsm_x4_t(bb, &Vs[kf * 16 + (lane & 15)][pd * 16 + (lane >> 4) * 8]);
                mma_bf16(oacc[pd * 2 + 0], af, bb[0], bb[1]);
                mma_bf16(oacc[pd * 2 + 1], af, bb[2], bb[3]);
            }
        }
    }

    // ---- finalize ----
    l1 += __shfl_xor_sync(0xFFFFFFFFu, l1, 1);
    l1 += __shfl_xor_sync(0xFFFFFFFFu, l1, 2);
    l2 += __shfl_xor_sync(0xFFFFFFFFu, l2, 1);
    l2 += __shfl_xor_sync(0xFFFFFFFFu, l2, 2);
    float inv1 = 1.f / l1;
    float inv2 = 1.f / l2;

    size_t ob1 = (size_t)(b * SEQ + r1g) * CDIM + h * HDIM;
    size_t ob2 = (size_t)(b * SEQ + r2g) * CDIM + h * HDIM;
    #pragma unroll
    for (int nb = 0; nb < 8; nb++) {
        int c = nb * 8 + (lane & 3) * 2;
        split_bf16(oacc[nb][0] * inv1, outh + ob1 + c,     outl + ob1 + c);
        split_bf16(oacc[nb][1] * inv1, outh + ob1 + c + 1, outl + ob1 + c + 1);
        split_bf16(oacc[nb][2] * inv2, outh + ob2 + c,     outl + ob2 + c);
        split_bf16(oacc[nb][3] * inv2, outh + ob2 + c + 1, outl + ob2 + c + 1);
    }
}

// ---------------- launch ----------------
extern "C" void kernel_launch(void* const* d_in, const int* in_sizes, int n_in,
                              void* d_out, int out_size)
{
    const float* x           = (const float*)d_in[0];
    const float* ln1_w       = (const float*)d_in[1];
    const float* ln1_b       = (const float*)d_in[2];
    const float* W_attn      = (const float*)d_in[3];
    const float* b_attn      = (const float*)d_in[4];
    const float* W_attn_proj = (const float*)d_in[5];
    const float* b_attn_proj = (const float*)d_in[6];
    const float* ln2_w       = (const float*)d_in[7];
    const float* ln2_b       = (const float*)d_in[8];
    const float* W_fc        = (const float*)d_in[9];
    const float* b_fc        = (const float*)d_in[10];
    const float* W_mlp_proj  = (const float*)d_in[11];
    const float* b_mlp_proj  = (const float*)d_in[12];
    float* out = (float*)d_out;

    bf16 *p_lnh, *p_lnl, *p_qkvh, *p_qkvl, *p_atth, *p_attl, *p_fch, *p_fcl;
    bf16 *p_wah, *p_wph, *p_wfh, *p_wmh;
    float *p_x1;
    cudaGetSymbolAddress((void**)&p_lnh,  g_lnh);
    cudaGetSymbolAddress((void**)&p_lnl,  g_lnl);
    cudaGetSymbolAddress((void**)&p_qkvh, g_qkvh);
    cudaGetSymbolAddress((void**)&p_qkvl, g_qkvl);
    cudaGetSymbolAddress((void**)&p_atth, g_atth);
    cudaGetSymbolAddress((void**)&p_attl, g_attl);
    cudaGetSymbolAddress((void**)&p_x1,   g_x1);
    cudaGetSymbolAddress((void**)&p_fch,  g_fch);
    cudaGetSymbolAddress((void**)&p_fcl,  g_fcl);
    cudaGetSymbolAddress((void**)&p_wah,  g_wah);
    cudaGetSymbolAddress((void**)&p_wph,  g_wph);
    cudaGetSymbolAddress((void**)&p_wfh,  g_wfh);
    cudaGetSymbolAddress((void**)&p_wmh,  g_wmh);

    cvt_kernel<<<(CDIM * QKVDIM + 255) / 256, 256>>>(W_attn,      p_wah, CDIM * QKVDIM);
    cvt_kernel<<<(CDIM * CDIM   + 255) / 256, 256>>>(W_attn_proj, p_wph, CDIM * CDIM);
    cvt_kernel<<<(CDIM * FCDIM  + 255) / 256, 256>>>(W_fc,        p_wfh, CDIM * FCDIM);
    cvt_kernel<<<(FCDIM * CDIM  + 255) / 256, 256>>>(W_mlp_proj,  p_wmh, FCDIM * CDIM);

    ln_kernel<<<MROWS, 256>>>(x, ln1_w, ln1_b, p_lnh, p_lnl);

    hgemm<3><<<dim3(QKVDIM / 128, MROWS / 128), 256>>>(p_lnh, p_lnl, p_wah,
        b_attn, (const float*)0, (float*)0, p_qkvh, p_qkvl, MROWS, QKVDIM, CDIM);

    fattn_kernel<<<dim3(SEQ / 64, NHEAD, BATCH), 128>>>(p_qkvh, p_qkvl, p_atth, p_attl);

    hgemm<2><<<dim3(CDIM / 128, MROWS / 128), 256>>>(p_atth, p_attl, p_wph,
        b_attn_proj, x, p_x1, (bf16*)0, (bf16*)0, MROWS, CDIM, CDIM);

    ln_kernel<<<MROWS, 256>>>(p_x1, ln2_w, ln2_b, p_lnh, p_lnl);

    hgemm<1><<<dim3(FCDIM / 128, MROWS / 128), 256>>>(p_lnh, p_lnl, p_wfh,
        b_fc, (const float*)0, (float*)0, p_fch, p_fcl, MROWS, FCDIM, CDIM);

    hgemm<2><<<dim3(CDIM / 128, MROWS / 128), 256>>>(p_fch, p_fcl, p_wmh,
        b_mlp_proj, p_x1, out, (bf16*)0, (bf16*)0, MROWS, CDIM, FCDIM);
}

// round 7
// speedup vs baseline: 3.4690x; 1.0120x over previous
#include <cuda_runtime.h>
#include <cuda_fp16.h>
#include <stdint.h>
#include <math.h>

#define BATCH 4
#define SEQ   2048
#define CDIM  768
#define NHEAD 12
#define HDIM  64
#define MROWS 8192
#define QKVDIM 2304
#define FCDIM  3072

typedef __half f16;

// ---------------- device scratch ----------------
__device__ f16   g_lnh[MROWS*CDIM];
__device__ f16   g_lnl[MROWS*CDIM];
__device__ f16   g_qkvh[MROWS*QKVDIM];
__device__ f16   g_qkvl[MROWS*QKVDIM];
__device__ f16   g_atth[MROWS*CDIM];
__device__ f16   g_attl[MROWS*CDIM];
__device__ float g_x1[MROWS*CDIM];
__device__ f16   g_fch[MROWS*FCDIM];
__device__ f16   g_fcl[MROWS*FCDIM];
__device__ f16   g_wah[CDIM*QKVDIM];
__device__ f16   g_wph[CDIM*CDIM];
__device__ f16   g_wfh[CDIM*FCDIM];
__device__ f16   g_wmh[FCDIM*CDIM];

__device__ __forceinline__ void split_f16(float x, f16* h, f16* l)
{
    f16 hh = __float2half_rn(x);
    *h = hh;
    *l = __float2half_rn(x - __half2float(hh));
}

__device__ __forceinline__ uint32_t packh(float x, float y)
{
    __half2 t = __floats2half2_rn(x, y);
    return *(uint32_t*)&t;
}

// ---------------- fp32 -> fp16 weight conversion (8 elems/thread) ----------------
__global__ void cvt_kernel(const float* __restrict__ src, f16* __restrict__ hi, int n8)
{
    int i = blockIdx.x * 256 + threadIdx.x;
    if (i < n8) {
        float4 a = ((const float4*)src)[2 * i];
        float4 b = ((const float4*)src)[2 * i + 1];
        __half2 h0 = __floats2half2_rn(a.x, a.y);
        __half2 h1 = __floats2half2_rn(a.z, a.w);
        __half2 h2 = __floats2half2_rn(b.x, b.y);
        __half2 h3 = __floats2half2_rn(b.z, b.w);
        uint4 o;
        o.x = *(uint32_t*)&h0;
        o.y = *(uint32_t*)&h1;
        o.z = *(uint32_t*)&h2;
        o.w = *(uint32_t*)&h3;
        ((uint4*)hi)[i] = o;
    }
}

// ---------------- LayerNorm ----------------
__global__ __launch_bounds__(256) void ln_kernel(
    const float* __restrict__ x, const float* __restrict__ gw,
    const float* __restrict__ gb, f16* __restrict__ oh, f16* __restrict__ ol)
{
    __shared__ float ss[8];
    __shared__ float ss2[8];
    int row = blockIdx.x;
    const float* xr = x + (size_t)row * CDIM;
    float s = 0.f, s2 = 0.f;
    for (int i = threadIdx.x; i < CDIM; i += 256) {
        float t = xr[i];
        s += t;
        s2 += t * t;
    }
    for (int o = 16; o > 0; o >>= 1) {
        s  += __shfl_xor_sync(0xFFFFFFFFu, s,  o);
        s2 += __shfl_xor_sync(0xFFFFFFFFu, s2, o);
    }
    int wid = threadIdx.x >> 5;
    int lane = threadIdx.x & 31;
    if (lane == 0) {
        ss[wid] = s;
        ss2[wid] = s2;
    }
    __syncthreads();
    if (threadIdx.x == 0) {
        float a = 0.f, a2 = 0.f;
        for (int i = 0; i < 8; i++) {
            a += ss[i];
            a2 += ss2[i];
        }
        ss[0] = a;
        ss2[0] = a2;
    }
    __syncthreads();
    float mean = ss[0] * (1.f / CDIM);
    float var  = ss2[0] * (1.f / CDIM) - mean * mean;
    if (var < 0.f) var = 0.f;
    float inv = 1.f / (sqrtf(var) + 1e-6f);
    for (int i = threadIdx.x; i < CDIM; i += 256) {
        float v = gw[i] * (xr[i] - mean) * inv + gb[i];
        split_f16(v, oh + (size_t)row * CDIM + i, ol + (size_t)row * CDIM + i);
    }
}

// ---------------- mma helpers (asm operand lists spaced) ----------------
__device__ __forceinline__ void ldsm_x4(uint32_t* r, const void* p)
{
    uint32_t addr = (uint32_t)__cvta_generic_to_shared(p);
    asm volatile("ldmatrix.sync.aligned.m8n8.x4.shared.b16 { %0, %1, %2, %3 }, [ %4 ];"
        : "=r"(r[0]), "=r"(r[1]), "=r"(r[2]), "=r"(r[3]) : "r"(addr));
}

__device__ __forceinline__ void ldsm_x4_t(uint32_t* r, const void* p)
{
    uint32_t addr = (uint32_t)__cvta_generic_to_shared(p);
    asm volatile("ldmatrix.sync.aligned.m8n8.x4.trans.shared.b16 { %0, %1, %2, %3 }, [ %4 ];"
        : "=r"(r[0]), "=r"(r[1]), "=r"(r[2]), "=r"(r[3]) : "r"(addr));
}

__device__ __forceinline__ void mma_f16(float* c, const uint32_t* a,
                                        uint32_t b0, uint32_t b1)
{
    asm volatile("mma.sync.aligned.m16n8k16.row.col.f32.f16.f16.f32 "
        "{ %0, %1, %2, %3 }, { %4, %5, %6, %7 }, { %8, %9 }, { %0, %1, %2, %3 };"
        : "+f"(c[0]), "+f"(c[1]), "+f"(c[2]), "+f"(c[3])
        : "r"(a[0]), "r"(a[1]), "r"(a[2]), "r"(a[3]), "r"(b0), "r"(b1));
}

// ---------------- 2-phase split-fp16 tensor-core GEMM ----------------
// C = (A_hi + A_lo) @ B_hi + bias (+epilogue). fp32 accumulate.
// EPI: 0 = bias -> fp32
//      1 = bias + GELU -> f16 hi/lo
//      2 = bias + residual -> fp32
//      3 = bias -> f16 hi/lo
template<int EPI>
__global__ __launch_bounds__(256, 2) void hgemm(
    const f16* __restrict__ Ahi, const f16* __restrict__ Alo,
    const f16* __restrict__ Bhi,
    const float* __restrict__ bias, const float* __restrict__ res,
    float* __restrict__ Cf, f16* __restrict__ Chi, f16* __restrict__ Clo,
    int M, int N, int K)
{
    __shared__ f16 As[128][40];
    __shared__ f16 Bs[32][136];

    const int tid  = threadIdx.x;
    const int lane = tid & 31;
    const int warp = tid >> 5;
    const int wm = (warp >> 1) * 32;
    const int wn = (warp & 1) * 64;
    const int row0 = blockIdx.y * 128;
    const int col0 = blockIdx.x * 128;

    const int rA0 = tid >> 2;
    const int cA0 = (tid & 3) * 8;
    const int rA1 = rA0 + 64;
    const int rB0 = tid >> 4;
    const int cB0 = (tid & 15) * 8;
    const int rB1 = rB0 + 16;

    const int KT = K / 32;
    const int NT = 2 * KT;

    float acc[2][8][4];
    #pragma unroll
    for (int i = 0; i < 2; i++) {
        #pragma unroll
        for (int j = 0; j < 8; j++) {
            #pragma unroll
            for (int e = 0; e < 4; e++) {
                acc[i][j][e] = 0.f;
            }
        }
    }

    uint4 ra0, ra1, rb0, rb1;

    ra0 = *(const uint4*)(Ahi + (size_t)(row0 + rA0) * K + cA0);
    ra1 = *(const uint4*)(Ahi + (size_t)(row0 + rA1) * K + cA0);
    rb0 = *(const uint4*)(Bhi + (size_t)rB0 * N + col0 + cB0);
    rb1 = *(const uint4*)(Bhi + (size_t)rB1 * N + col0 + cB0);

    for (int it = 0; it < NT; ++it) {
        *(uint4*)&As[rA0][cA0] = ra0;
        *(uint4*)&As[rA1][cA0] = ra1;
        *(uint4*)&Bs[rB0][cB0] = rb0;
        *(uint4*)&Bs[rB1][cB0] = rb1;
        __syncthreads();

        if (it + 1 < NT) {
            int nit = it + 1;
            int ph = nit / KT;
            int kk = (nit % KT) * 32;
            const f16* Ap = (ph == 1) ? Alo : Ahi;
            ra0 = *(const uint4*)(Ap + (size_t)(row0 + rA0) * K + kk + cA0);
            ra1 = *(const uint4*)(Ap + (size_t)(row0 + rA1) * K + kk + cA0);
            rb0 = *(const uint4*)(Bhi + (size_t)(kk + rB0) * N + col0 + cB0);
            rb1 = *(const uint4*)(Bhi + (size_t)(kk + rB1) * N + col0 + cB0);
        }

        #pragma unroll
        for (int ks = 0; ks < 2; ++ks) {
            const int k0 = ks * 16;
            uint32_t af0[4];
            uint32_t af1[4];
            ldsm_x4(af0, &As[wm + (lane & 15)][k0 + (lane >> 4) * 8]);
            ldsm_x4(af1, &As[wm + 16 + (lane & 15)][k0 + (lane >> 4) * 8]);
            #pragma unroll
            for (int ni = 0; ni < 4; ++ni) {
                uint32_t bb[4];
                ldsm_x4_t(bb, &Bs[k0 + (lane & 15)][wn + ni * 16 + (lane >> 4) * 8]);
                mma_f16(acc[0][ni * 2 + 0], af0, bb[0], bb[1]);
                mma_f16(acc[0][ni * 2 + 1], af0, bb[2], bb[3]);
                mma_f16(acc[1][ni * 2 + 0], af1, bb[0], bb[1]);
                mma_f16(acc[1][ni * 2 + 1], af1, bb[2], bb[3]);
            }
        }
        __syncthreads();
    }

    #pragma unroll
    for (int mi = 0; mi < 2; ++mi) {
        #pragma unroll
        for (int n8 = 0; n8 < 8; ++n8) {
            #pragma unroll
            for (int e = 0; e < 4; ++e) {
                int r = row0 + wm + mi * 16 + (lane >> 2) + (e >> 1) * 8;
                int c = col0 + wn + n8 * 8 + (lane & 3) * 2 + (e & 1);
                float v = acc[mi][n8][e] + bias[c];
                size_t off = (size_t)r * N + c;
                if (EPI == 0) {
                    Cf[off] = v;
                } else if (EPI == 1) {
                    v = 0.5f * v * (1.f + erff(v * 0.7071067811865475f));
                    split_f16(v, Chi + off, Clo + off);
                } else if (EPI == 3) {
                    split_f16(v, Chi + off, Clo + off);
                } else {
                    Cf[off] = v + res[off];
                }
            }
        }
    }
}

// ---------------- Tensor-core flash attention (causal, fp16) ----------------
// grid: (SEQ/64, NHEAD, BATCH), 128 threads = 4 warps; warp owns 16 query rows.
// Scores: 2-phase (q_hi + q_lo) . k_hi via mma (scale folded into Q frags);
// P*V in fp16.
__global__ __launch_bounds__(128) void fattn_kernel(
    const f16* __restrict__ qkvh, const f16* __restrict__ qkvl,
    f16* __restrict__ outh, f16* __restrict__ outl)
{
    __shared__ f16 Qs[64][72];
    __shared__ f16 KsH[64][72];
    __shared__ f16 Vs[64][72];

    const int b = blockIdx.z;
    const int h = blockIdx.y;
    const int qb = blockIdx.x;
    const int tid = threadIdx.x;
    const int lane = tid & 31;
    const int warp = tid >> 5;
    const int row0 = qb * 64;

    const size_t base = (size_t)b * SEQ * QKVDIM;
    const __half2 sc2 = __floats2half2_rn(0.125f, 0.125f);

    // ---- stage Q (hi), extract frags (scaled), then lo ----
    #pragma unroll
    for (int i = 0; i < 4; i++) {
        int e = tid + i * 128;
        int r = e >> 3;
        int c = (e & 7) * 8;
        *(uint4*)&Qs[r][c] = *(const uint4*)(qkvh + base + (size_t)(row0 + r) * QKVDIM + h * HDIM + c);
    }
    __syncthreads();
    uint32_t qh[4][4];
    uint32_t ql[4][4];
    #pragma unroll
    for (int kf = 0; kf < 4; kf++) {
        ldsm_x4(qh[kf], &Qs[warp * 16 + (lane & 15)][kf * 16 + (lane >> 4) * 8]);
        #pragma unroll
        for (int e = 0; e < 4; e++) {
            __half2 t = *(__half2*)&qh[kf][e];
            t = __hmul2(t, sc2);
            qh[kf][e] = *(uint32_t*)&t;
        }
    }
    __syncthreads();
    #pragma unroll
    for (int i = 0; i < 4; i++) {
        int e = tid + i * 128;
        int r = e >> 3;
        int c = (e & 7) * 8;
        *(uint4*)&Qs[r][c] = *(const uint4*)(qkvl + base + (size_t)(row0 + r) * QKVDIM + h * HDIM + c);
    }
    __syncthreads();
    #pragma unroll
    for (int kf = 0; kf < 4; kf++) {
        ldsm_x4(ql[kf], &Qs[warp * 16 + (lane & 15)][kf * 16 + (lane >> 4) * 8]);
        #pragma unroll
        for (int e = 0; e < 4; e++) {
            __half2 t = *(__half2*)&ql[kf][e];
            t = __hmul2(t, sc2);
            ql[kf][e] = *(uint32_t*)&t;
        }
    }

    float oacc[8][4];
    #pragma unroll
    for (int nb = 0; nb < 8; nb++) {
        #pragma unroll
        for (int e = 0; e < 4; e++) {
            oacc[nb][e] = 0.f;
        }
    }
    float m1 = -1e30f, m2 = -1e30f;
    float l1 = 0.f, l2 = 0.f;

    const int r1g = row0 + warp * 16 + (lane >> 2);
    const int r2g = r1g + 8;

    for (int kt = 0; kt <= qb; kt++) {
        const int j0g = kt * 64;
        __syncthreads();
        #pragma unroll
        for (int i = 0; i < 4; i++) {
            int e = tid + i * 128;
            int r = e >> 3;
            int c = (e & 7) * 8;
            size_t goff = base + (size_t)(j0g + r) * QKVDIM + CDIM + h * HDIM + c;
            *(uint4*)&KsH[r][c] = *(const uint4*)(qkvh + goff);
            *(uint4*)&Vs[r][c]  = *(const uint4*)(qkvh + goff + CDIM);
        }
        __syncthreads();

        // ---- S = Q K^T (2 phases, scale pre-folded) ----
        float sacc[8][4];
        #pragma unroll
        for (int nb = 0; nb < 8; nb++) {
            #pragma unroll
            for (int e = 0; e < 4; e++) {
                sacc[nb][e] = 0.f;
            }
        }
        #pragma unroll
        for (int kf = 0; kf < 4; kf++) {
            const int d0 = kf * 16;
            #pragma unroll
            for (int p = 0; p < 4; p++) {
                const int j0 = p * 16;
                uint32_t bh[4];
                ldsm_x4(bh, &KsH[j0 + ((lane >> 4) << 3) + (lane & 7)][d0 + (((lane >> 3) & 1) << 3)]);
                mma_f16(sacc[p * 2 + 0], qh[kf], bh[0], bh[1]);
                mma_f16(sacc[p * 2 + 1], qh[kf], bh[2], bh[3]);
                mma_f16(sacc[p * 2 + 0], ql[kf], bh[0], bh[1]);
                mma_f16(sacc[p * 2 + 1], ql[kf], bh[2], bh[3]);
            }
        }

        // ---- causal mask (diagonal tile only) ----
        if (kt == qb) {
            #pragma unroll
            for (int nb = 0; nb < 8; nb++) {
                int jg = j0g + nb * 8 + (lane & 3) * 2;
                if (jg     > r1g) sacc[nb][0] = -1e30f;
                if (jg + 1 > r1g) sacc[nb][1] = -1e30f;
                if (jg     > r2g) sacc[nb][2] = -1e30f;
                if (jg + 1 > r2g) sacc[nb][3] = -1e30f;
            }
        }

        // ---- online softmax ----
        float mx1 = -1e30f, mx2 = -1e30f;
        #pragma unroll
        for (int nb = 0; nb < 8; nb++) {
            mx1 = fmaxf(mx1, fmaxf(sacc[nb][0], sacc[nb][1]));
            mx2 = fmaxf(mx2, fmaxf(sacc[nb][2], sacc[nb][3]));
        }
        mx1 = fmaxf(mx1, __shfl_xor_sync(0xFFFFFFFFu, mx1, 1));
        mx1 = fmaxf(mx1, __shfl_xor_sync(0xFFFFFFFFu, mx1, 2));
        mx2 = fmaxf(mx2, __shfl_xor_sync(0xFFFFFFFFu, mx2, 1));
        mx2 = fmaxf(mx2, __shfl_xor_sync(0xFFFFFFFFu, mx2, 2));

        float nm1 = fmaxf(m1, mx1);
        float nm2 = fmaxf(m2, mx2);
        float co1 = __expf(m1 - nm1);
        float co2 = __expf(m2 - nm2);
        m1 = nm1;
        m2 = nm2;

        uint32_t pa1[8];
        uint32_t pa2[8];
        float ps1 = 0.f, ps2 = 0.f;
        #pragma unroll
        for (int nb = 0; nb < 8; nb++) {
            float p0 = __expf(sacc[nb][0] - m1);
            float p1 = __expf(sacc[nb][1] - m1);
            float p2 = __expf(sacc[nb][2] - m2);
            float p3 = __expf(sacc[nb][3] - m2);
            ps1 += p0 + p1;
            ps2 += p2 + p3;
            pa1[nb] = packh(p0, p1);
            pa2[nb] = packh(p2, p3);
        }
        l1 = l1 * co1 + ps1;
        l2 = l2 * co2 + ps2;
        #pragma unroll
        for (int nb = 0; nb < 8; nb++) {
            oacc[nb][0] *= co1;
            oacc[nb][1] *= co1;
            oacc[nb][2] *= co2;
            oacc[nb][3] *= co2;
        }

        // ---- O += P V ----
        #pragma unroll
        for (int kf = 0; kf < 4; kf++) {
            uint32_t af[4];
            af[0] = pa1[kf * 2];
            af[1] = pa2[kf * 2];
            af[2] = pa1[kf * 2 + 1];
            af[3] = pa2[kf * 2 + 1];
            #pragma unroll
            for (int pd = 0; pd < 4; pd++) {
                uint32_t bb[4];
                ldsm_x4_t(bb, &Vs[kf * 16 + (lane & 15)][pd * 16 + (lane >> 4) * 8]);
                mma_f16(oacc[pd * 2 + 0], af, bb[0], bb[1]);
                mma_f16(oacc[pd * 2 + 1], af, bb[2], bb[3]);
            }
        }
    }

    // ---- finalize ----
    l1 += __shfl_xor_sync(0xFFFFFFFFu, l1, 1);
    l1 += __shfl_xor_sync(0xFFFFFFFFu, l1, 2);
    l2 += __shfl_xor_sync(0xFFFFFFFFu, l2, 1);
    l2 += __shfl_xor_sync(0xFFFFFFFFu, l2, 2);
    float inv1 = 1.f / l1;
    float inv2 = 1.f / l2;

    size_t ob1 = (size_t)(b * SEQ + r1g) * CDIM + h * HDIM;
    size_t ob2 = (size_t)(b * SEQ + r2g) * CDIM + h * HDIM;
    #pragma unroll
    for (int nb = 0; nb < 8; nb++) {
        int c = nb * 8 + (lane & 3) * 2;
        split_f16(oacc[nb][0] * inv1, outh + ob1 + c,     outl + ob1 + c);
        split_f16(oacc[nb][1] * inv1, outh + ob1 + c + 1, outl + ob1 + c + 1);
        split_f16(oacc[nb][2] * inv2, outh + ob2 + c,     outl + ob2 + c);
        split_f16(oacc[nb][3] * inv2, outh + ob2 + c + 1, outl + ob2 + c + 1);
    }
}

// ---------------- launch ----------------
extern "C" void kernel_launch(void* const* d_in, const int* in_sizes, int n_in,
                              void* d_out, int out_size)
{
    const float* x           = (const float*)d_in[0];
    const float* ln1_w       = (const float*)d_in[1];
    const float* ln1_b       = (const float*)d_in[2];
    const float* W_attn      = (const float*)d_in[3];
    const float* b_attn      = (const float*)d_in[4];
    const float* W_attn_proj = (const float*)d_in[5];
    const float* b_attn_proj = (const float*)d_in[6];
    const float* ln2_w       = (const float*)d_in[7];
    const float* ln2_b       = (const float*)d_in[8];
    const float* W_fc        = (const float*)d_in[9];
    const float* b_fc        = (const float*)d_in[10];
    const float* W_mlp_proj  = (const float*)d_in[11];
    const float* b_mlp_proj  = (const float*)d_in[12];
    float* out = (float*)d_out;

    f16 *p_lnh, *p_lnl, *p_qkvh, *p_qkvl, *p_atth, *p_attl, *p_fch, *p_fcl;
    f16 *p_wah, *p_wph, *p_wfh, *p_wmh;
    float *p_x1;
    cudaGetSymbolAddress((void**)&p_lnh,  g_lnh);
    cudaGetSymbolAddress((void**)&p_lnl,  g_lnl);
    cudaGetSymbolAddress((void**)&p_qkvh, g_qkvh);
    cudaGetSymbolAddress((void**)&p_qkvl, g_qkvl);
    cudaGetSymbolAddress((void**)&p_atth, g_atth);
    cudaGetSymbolAddress((void**)&p_attl, g_attl);
    cudaGetSymbolAddress((void**)&p_x1,   g_x1);
    cudaGetSymbolAddress((void**)&p_fch,  g_fch);
    cudaGetSymbolAddress((void**)&p_fcl,  g_fcl);
    cudaGetSymbolAddress((void**)&p_wah,  g_wah);
    cudaGetSymbolAddress((void**)&p_wph,  g_wph);
    cudaGetSymbolAddress((void**)&p_wfh,  g_wfh);
    cudaGetSymbolAddress((void**)&p_wmh,  g_wmh);

    cvt_kernel<<<(CDIM * QKVDIM / 8 + 255) / 256, 256>>>(W_attn,      p_wah, CDIM * QKVDIM / 8);
    cvt_kernel<<<(CDIM * CDIM   / 8 + 255) / 256, 256>>>(W_attn_proj, p_wph, CDIM * CDIM / 8);
    cvt_kernel<<<(CDIM * FCDIM  / 8 + 255) / 256, 256>>>(W_fc,        p_wfh, CDIM * FCDIM / 8);
    cvt_kernel<<<(FCDIM * CDIM  / 8 + 255) / 256, 256>>>(W_mlp_proj,  p_wmh, FCDIM * CDIM / 8);

    ln_kernel<<<MROWS, 256>>>(x, ln1_w, ln1_b, p_lnh, p_lnl);

    hgemm<3><<<dim3(QKVDIM / 128, MROWS / 128), 256>>>(p_lnh, p_lnl, p_wah,
        b_attn, (const float*)0, (float*)0, p_qkvh, p_qkvl, MROWS, QKVDIM, CDIM);

    fattn_kernel<<<dim3(SEQ / 64, NHEAD, BATCH), 128>>>(p_qkvh, p_qkvl, p_atth, p_attl);

    hgemm<2><<<dim3(CDIM / 128, MROWS / 128), 256>>>(p_atth, p_attl, p_wph,
        b_attn_proj, x, p_x1, (f16*)0, (f16*)0, MROWS, CDIM, CDIM);

    ln_kernel<<<MROWS, 256>>>(p_x1, ln2_w, ln2_b, p_lnh, p_lnl);

    hgemm<1><<<dim3(FCDIM / 128, MROWS / 128), 256>>>(p_lnh, p_lnl, p_wfh,
        b_fc, (const float*)0, (float*)0, p_fch, p_fcl, MROWS, FCDIM, CDIM);

    hgemm<2><<<dim3(CDIM / 128, MROWS / 128), 256>>>(p_fch, p_fcl, p_wmh,
        b_mlp_proj, p_x1, out, (f16*)0, (f16*)0, MROWS, CDIM, FCDIM);
}

// round 8
// speedup vs baseline: 5.9081x; 1.7031x over previous
#include <cuda_runtime.h>
#include <cuda_fp16.h>
#include <stdint.h>
#include <math.h>

#define BATCH 4
#define SEQ   2048
#define CDIM  768
#define NHEAD 12
#define HDIM  64
#define MROWS 8192
#define QKVDIM 2304
#define FCDIM  3072

typedef __half f16;

// ---------------- device scratch ----------------
__device__ f16   g_lnh[MROWS*CDIM];
__device__ f16   g_qkvh[MROWS*QKVDIM];
__device__ f16   g_qkvl[MROWS*QKVDIM];
__device__ f16   g_atth[MROWS*CDIM];
__device__ float g_x1[MROWS*CDIM];
__device__ f16   g_fch[MROWS*FCDIM];
__device__ f16   g_wah[CDIM*QKVDIM];
__device__ f16   g_wph[CDIM*CDIM];
__device__ f16   g_wfh[CDIM*FCDIM];
__device__ f16   g_wmh[FCDIM*CDIM];

__device__ __forceinline__ void split_f16(float x, f16* h, f16* l)
{
    f16 hh = __float2half_rn(x);
    *h = hh;
    *l = __float2half_rn(x - __half2float(hh));
}

__device__ __forceinline__ uint32_t packh(float x, float y)
{
    __half2 t = __floats2half2_rn(x, y);
    return *(uint32_t*)&t;
}

// ---------------- fp32 -> fp16 weight conversion (8 elems/thread) ----------------
__global__ void cvt_kernel(const float* __restrict__ src, f16* __restrict__ hi, int n8)
{
    int i = blockIdx.x * 256 + threadIdx.x;
    if (i < n8) {
        float4 a = ((const float4*)src)[2 * i];
        float4 b = ((const float4*)src)[2 * i + 1];
        __half2 h0 = __floats2half2_rn(a.x, a.y);
        __half2 h1 = __floats2half2_rn(a.z, a.w);
        __half2 h2 = __floats2half2_rn(b.x, b.y);
        __half2 h3 = __floats2half2_rn(b.z, b.w);
        uint4 o;
        o.x = *(uint32_t*)&h0;
        o.y = *(uint32_t*)&h1;
        o.z = *(uint32_t*)&h2;
        o.w = *(uint32_t*)&h3;
        ((uint4*)hi)[i] = o;
    }
}

// ---------------- LayerNorm (fp16 hi output only) ----------------
__global__ __launch_bounds__(256) void ln_kernel(
    const float* __restrict__ x, const float* __restrict__ gw,
    const float* __restrict__ gb, f16* __restrict__ oh)
{
    __shared__ float ss[8];
    __shared__ float ss2[8];
    int row = blockIdx.x;
    const float* xr = x + (size_t)row * CDIM;
    float s = 0.f, s2 = 0.f;
    for (int i = threadIdx.x; i < CDIM; i += 256) {
        float t = xr[i];
        s += t;
        s2 += t * t;
    }
    for (int o = 16; o > 0; o >>= 1) {
        s  += __shfl_xor_sync(0xFFFFFFFFu, s,  o);
        s2 += __shfl_xor_sync(0xFFFFFFFFu, s2, o);
    }
    int wid = threadIdx.x >> 5;
    int lane = threadIdx.x & 31;
    if (lane == 0) {
        ss[wid] = s;
        ss2[wid] = s2;
    }
    __syncthreads();
    if (threadIdx.x == 0) {
        float a = 0.f, a2 = 0.f;
        for (int i = 0; i < 8; i++) {
            a += ss[i];
            a2 += ss2[i];
        }
        ss[0] = a;
        ss2[0] = a2;
    }
    __syncthreads();
    float mean = ss[0] * (1.f / CDIM);
    float var  = ss2[0] * (1.f / CDIM) - mean * mean;
    if (var < 0.f) var = 0.f;
    float inv = 1.f / (sqrtf(var) + 1e-6f);
    for (int i = threadIdx.x; i < CDIM; i += 256) {
        float v = gw[i] * (xr[i] - mean) * inv + gb[i];
        oh[(size_t)row * CDIM + i] = __float2half_rn(v);
    }
}

// ---------------- mma helpers (asm operand lists spaced) ----------------
__device__ __forceinline__ void ldsm_x4(uint32_t* r, const void* p)
{
    uint32_t addr = (uint32_t)__cvta_generic_to_shared(p);
    asm volatile("ldmatrix.sync.aligned.m8n8.x4.shared.b16 { %0, %1, %2, %3 }, [ %4 ];"
        : "=r"(r[0]), "=r"(r[1]), "=r"(r[2]), "=r"(r[3]) : "r"(addr));
}

__device__ __forceinline__ void ldsm_x4_t(uint32_t* r, const void* p)
{
    uint32_t addr = (uint32_t)__cvta_generic_to_shared(p);
    asm volatile("ldmatrix.sync.aligned.m8n8.x4.trans.shared.b16 { %0, %1, %2, %3 }, [ %4 ];"
        : "=r"(r[0]), "=r"(r[1]), "=r"(r[2]), "=r"(r[3]) : "r"(addr));
}

__device__ __forceinline__ void mma_f16(float* c, const uint32_t* a,
                                        uint32_t b0, uint32_t b1)
{
    asm volatile("mma.sync.aligned.m16n8k16.row.col.f32.f16.f16.f32 "
        "{ %0, %1, %2, %3 }, { %4, %5, %6, %7 }, { %8, %9 }, { %0, %1, %2, %3 };"
        : "+f"(c[0]), "+f"(c[1]), "+f"(c[2]), "+f"(c[3])
        : "r"(a[0]), "r"(a[1]), "r"(a[2]), "r"(a[3]), "r"(b0), "r"(b1));
}

// ---------------- 1-phase fp16 tensor-core GEMM ----------------
// C = A_hi @ B_hi + bias (+epilogue). fp32 accumulate.
// EPI: 1 = bias + GELU -> f16 hi
//      2 = bias + residual -> fp32
//      3 = bias -> f16 hi (+ lo plane for columns < CDIM, i.e. Q)
template<int EPI>
__global__ __launch_bounds__(256, 2) void hgemm(
    const f16* __restrict__ Ahi,
    const f16* __restrict__ Bhi,
    const float* __restrict__ bias, const float* __restrict__ res,
    float* __restrict__ Cf, f16* __restrict__ Chi, f16* __restrict__ Clo,
    int M, int N, int K)
{
    __shared__ f16 As[128][40];
    __shared__ f16 Bs[32][136];

    const int tid  = threadIdx.x;
    const int lane = tid & 31;
    const int warp = tid >> 5;
    const int wm = (warp >> 1) * 32;
    const int wn = (warp & 1) * 64;
    const int row0 = blockIdx.y * 128;
    const int col0 = blockIdx.x * 128;

    const int rA0 = tid >> 2;
    const int cA0 = (tid & 3) * 8;
    const int rA1 = rA0 + 64;
    const int rB0 = tid >> 4;
    const int cB0 = (tid & 15) * 8;
    const int rB1 = rB0 + 16;

    const int KT = K / 32;

    float acc[2][8][4];
    #pragma unroll
    for (int i = 0; i < 2; i++) {
        #pragma unroll
        for (int j = 0; j < 8; j++) {
            #pragma unroll
            for (int e = 0; e < 4; e++) {
                acc[i][j][e] = 0.f;
            }
        }
    }

    uint4 ra0, ra1, rb0, rb1;

    ra0 = *(const uint4*)(Ahi + (size_t)(row0 + rA0) * K + cA0);
    ra1 = *(const uint4*)(Ahi + (size_t)(row0 + rA1) * K + cA0);
    rb0 = *(const uint4*)(Bhi + (size_t)rB0 * N + col0 + cB0);
    rb1 = *(const uint4*)(Bhi + (size_t)rB1 * N + col0 + cB0);

    for (int it = 0; it < KT; ++it) {
        *(uint4*)&As[rA0][cA0] = ra0;
        *(uint4*)&As[rA1][cA0] = ra1;
        *(uint4*)&Bs[rB0][cB0] = rb0;
        *(uint4*)&Bs[rB1][cB0] = rb1;
        __syncthreads();

        if (it + 1 < KT) {
            int kk = (it + 1) * 32;
            ra0 = *(const uint4*)(Ahi + (size_t)(row0 + rA0) * K + kk + cA0);
            ra1 = *(const uint4*)(Ahi + (size_t)(row0 + rA1) * K + kk + cA0);
            rb0 = *(const uint4*)(Bhi + (size_t)(kk + rB0) * N + col0 + cB0);
            rb1 = *(const uint4*)(Bhi + (size_t)(kk + rB1) * N + col0 + cB0);
        }

        #pragma unroll
        for (int ks = 0; ks < 2; ++ks) {
            const int k0 = ks * 16;
            uint32_t af0[4];
            uint32_t af1[4];
            ldsm_x4(af0, &As[wm + (lane & 15)][k0 + (lane >> 4) * 8]);
            ldsm_x4(af1, &As[wm + 16 + (lane & 15)][k0 + (lane >> 4) * 8]);
            #pragma unroll
            for (int ni = 0; ni < 4; ++ni) {
                uint32_t bb[4];
                ldsm_x4_t(bb, &Bs[k0 + (lane & 15)][wn + ni * 16 + (lane >> 4) * 8]);
                mma_f16(acc[0][ni * 2 + 0], af0, bb[0], bb[1]);
                mma_f16(acc[0][ni * 2 + 1], af0, bb[2], bb[3]);
                mma_f16(acc[1][ni * 2 + 0], af1, bb[0], bb[1]);
                mma_f16(acc[1][ni * 2 + 1], af1, bb[2], bb[3]);
            }
        }
        __syncthreads();
    }

    #pragma unroll
    for (int mi = 0; mi < 2; ++mi) {
        #pragma unroll
        for (int n8 = 0; n8 < 8; ++n8) {
            #pragma unroll
            for (int e = 0; e < 4; ++e) {
                int r = row0 + wm + mi * 16 + (lane >> 2) + (e >> 1) * 8;
                int c = col0 + wn + n8 * 8 + (lane & 3) * 2 + (e & 1);
                float v = acc[mi][n8][e] + bias[c];
                size_t off = (size_t)r * N + c;
                if (EPI == 1) {
                    v = 0.5f * v * (1.f + erff(v * 0.7071067811865475f));
                    Chi[off] = __float2half_rn(v);
                } else if (EPI == 3) {
                    if (c < CDIM) {
                        split_f16(v, Chi + off, Clo + off);
                    } else {
                        Chi[off] = __float2half_rn(v);
                    }
                } else {
                    Cf[off] = v + res[off];
                }
            }
        }
    }
}

// ---------------- Tensor-core flash attention (causal, fp16) ----------------
// grid: (SEQ/64, NHEAD, BATCH), 128 threads = 4 warps; warp owns 16 query rows.
// Scores: 2-phase (q_hi + q_lo) . k_hi via mma (scale folded into Q frags);
// P*V in fp16. Output: fp16 hi only.
__global__ __launch_bounds__(128) void fattn_kernel(
    const f16* __restrict__ qkvh, const f16* __restrict__ qkvl,
    f16* __restrict__ outh)
{
    __shared__ f16 Qs[64][72];
    __shared__ f16 KsH[64][72];
    __shared__ f16 Vs[64][72];

    const int b = blockIdx.z;
    const int h = blockIdx.y;
    const int qb = blockIdx.x;
    const int tid = threadIdx.x;
    const int lane = tid & 31;
    const int warp = tid >> 5;
    const int row0 = qb * 64;

    const size_t base = (size_t)b * SEQ * QKVDIM;
    const __half2 sc2 = __floats2half2_rn(0.125f, 0.125f);

    // ---- stage Q (hi), extract frags (scaled), then lo ----
    #pragma unroll
    for (int i = 0; i < 4; i++) {
        int e = tid + i * 128;
        int r = e >> 3;
        int c = (e & 7) * 8;
        *(uint4*)&Qs[r][c] = *(const uint4*)(qkvh + base + (size_t)(row0 + r) * QKVDIM + h * HDIM + c);
    }
    __syncthreads();
    uint32_t qh[4][4];
    uint32_t ql[4][4];
    #pragma unroll
    for (int kf = 0; kf < 4; kf++) {
        ldsm_x4(qh[kf], &Qs[warp * 16 + (lane & 15)][kf * 16 + (lane >> 4) * 8]);
        #pragma unroll
        for (int e = 0; e < 4; e++) {
            __half2 t = *(__half2*)&qh[kf][e];
            t = __hmul2(t, sc2);
            qh[kf][e] = *(uint32_t*)&t;
        }
    }
    __syncthreads();
    #pragma unroll
    for (int i = 0; i < 4; i++) {
        int e = tid + i * 128;
        int r = e >> 3;
        int c = (e & 7) * 8;
        *(uint4*)&Qs[r][c] = *(const uint4*)(qkvl + base + (size_t)(row0 + r) * QKVDIM + h * HDIM + c);
    }
    __syncthreads();
    #pragma unroll
    for (int kf = 0; kf < 4; kf++) {
        ldsm_x4(ql[kf], &Qs[warp * 16 + (lane & 15)][kf * 16 + (lane >> 4) * 8]);
        #pragma unroll
        for (int e = 0; e < 4; e++) {
            __half2 t = *(__half2*)&ql[kf][e];
            t = __hmul2(t, sc2);
            ql[kf][e] = *(uint32_t*)&t;
        }
    }

    float oacc[8][4];
    #pragma unroll
    for (int nb = 0; nb < 8; nb++) {
        #pragma unroll
        for (int e = 0; e < 4; e++) {
            oacc[nb][e] = 0.f;
        }
    }
    float m1 = -1e30f, m2 = -1e30f;
    float l1 = 0.f, l2 = 0.f;

    const int r1g = row0 + warp * 16 + (lane >> 2);
    const int r2g = r1g + 8;

    for (int kt = 0; kt <= qb; kt++) {
        const int j0g = kt * 64;
        __syncthreads();
        #pragma unroll
        for (int i = 0; i < 4; i++) {
            int e = tid + i * 128;
            int r = e >> 3;
            int c = (e & 7) * 8;
            size_t goff = base + (size_t)(j0g + r) * QKVDIM + CDIM + h * HDIM + c;
            *(uint4*)&KsH[r][c] = *(const uint4*)(qkvh + goff);
            *(uint4*)&Vs[r][c]  = *(const uint4*)(qkvh + goff + CDIM);
        }
        __syncthreads();

        // ---- S = Q K^T (2 phases, scale pre-folded) ----
        float sacc[8][4];
        #pragma unroll
        for (int nb = 0; nb < 8; nb++) {
            #pragma unroll
            for (int e = 0; e < 4; e++) {
                sacc[nb][e] = 0.f;
            }
        }
        #pragma unroll
        for (int kf = 0; kf < 4; kf++) {
            const int d0 = kf * 16;
            #pragma unroll
            for (int p = 0; p < 4; p++) {
                const int j0 = p * 16;
                uint32_t bh[4];
                ldsm_x4(bh, &KsH[j0 + ((lane >> 4) << 3) + (lane & 7)][d0 + (((lane >> 3) & 1) << 3)]);
                mma_f16(sacc[p * 2 + 0], qh[kf], bh[0], bh[1]);
                mma_f16(sacc[p * 2 + 1], qh[kf], bh[2], bh[3]);
                mma_f16(sacc[p * 2 + 0], ql[kf], bh[0], bh[1]);
                mma_f16(sacc[p * 2 + 1], ql[kf], bh[2], bh[3]);
            }
        }

        // ---- causal mask (diagonal tile only) ----
        if (kt == qb) {
            #pragma unroll
            for (int nb = 0; nb < 8; nb++) {
                int jg = j0g + nb * 8 + (lane & 3) * 2;
                if (jg     > r1g) sacc[nb][0] = -1e30f;
                if (jg + 1 > r1g) sacc[nb][1] = -1e30f;
                if (jg     > r2g) sacc[nb][2] = -1e30f;
                if (jg + 1 > r2g) sacc[nb][3] = -1e30f;
            }
        }

        // ---- online softmax ----
        float mx1 = -1e30f, mx2 = -1e30f;
        #pragma unroll
        for (int nb = 0; nb < 8; nb++) {
            mx1 = fmaxf(mx1, fmaxf(sacc[nb][0], sacc[nb][1]));
            mx2 = fmaxf(mx2, fmaxf(sacc[nb][2], sacc[nb][3]));
        }
        mx1 = fmaxf(mx1, __shfl_xor_sync(0xFFFFFFFFu, mx1, 1));
        mx1 = fmaxf(mx1, __shfl_xor_sync(0xFFFFFFFFu, mx1, 2));
        mx2 = fmaxf(mx2, __shfl_xor_sync(0xFFFFFFFFu, mx2, 1));
        mx2 = fmaxf(mx2, __shfl_xor_sync(0xFFFFFFFFu, mx2, 2));

        float nm1 = fmaxf(m1, mx1);
        float nm2 = fmaxf(m2, mx2);
        float co1 = __expf(m1 - nm1);
        float co2 = __expf(m2 - nm2);
        m1 = nm1;
        m2 = nm2;

        uint32_t pa1[8];
        uint32_t pa2[8];
        float ps1 = 0.f, ps2 = 0.f;
        #pragma unroll
        for (int nb = 0; nb < 8; nb++) {
            float p0 = __expf(sacc[nb][0] - m1);
            float p1 = __expf(sacc[nb][1] - m1);
            float p2 = __expf(sacc[nb][2] - m2);
            float p3 = __expf(sacc[nb][3] - m2);
            ps1 += p0 + p1;
            ps2 += p2 + p3;
            pa1[nb] = packh(p0, p1);
            pa2[nb] = packh(p2, p3);
        }
        l1 = l1 * co1 + ps1;
        l2 = l2 * co2 + ps2;
        #pragma unroll
        for (int nb = 0; nb < 8; nb++) {
            oacc[nb][0] *= co1;
            oacc[nb][1] *= co1;
            oacc[nb][2] *= co2;
            oacc[nb][3] *= co2;
        }

        // ---- O += P V ----
        #pragma unroll
        for (int kf = 0; kf < 4; kf++) {
            uint32_t af[4];
            af[0] = pa1[kf * 2];
            af[1] = pa2[kf * 2];
            af[2] = pa1[kf * 2 + 1];
            af[3] = pa2[kf * 2 + 1];
            #pragma unroll
            for (int pd = 0; pd < 4; pd++) {
                uint32_t bb[4];
                ldsm_x4_t(bb, &Vs[kf * 16 + (lane & 15)][pd * 16 + (lane >> 4) * 8]);
                mma_f16(oacc[pd * 2 + 0], af, bb[0], bb[1]);
                mma_f16(oacc[pd * 2 + 1], af, bb[2], bb[3]);
            }
        }
    }

    // ---- finalize ----
    l1 += __shfl_xor_sync(0xFFFFFFFFu, l1, 1);
    l1 += __shfl_xor_sync(0xFFFFFFFFu, l1, 2);
    l2 += __shfl_xor_sync(0xFFFFFFFFu, l2, 1);
    l2 += __shfl_xor_sync(0xFFFFFFFFu, l2, 2);
    float inv1 = 1.f / l1;
    float inv2 = 1.f / l2;

    size_t ob1 = (size_t)(b * SEQ + r1g) * CDIM + h * HDIM;
    size_t ob2 = (size_t)(b * SEQ + r2g) * CDIM + h * HDIM;
    #pragma unroll
    for (int nb = 0; nb < 8; nb++) {
        int c = nb * 8 + (lane & 3) * 2;
        outh[ob1 + c    ] = __float2half_rn(oacc[nb][0] * inv1);
        outh[ob1 + c + 1] = __float2half_rn(oacc[nb][1] * inv1);
        outh[ob2 + c    ] = __float2half_rn(oacc[nb][2] * inv2);
        outh[ob2 + c + 1] = __float2half_rn(oacc[nb][3] * inv2);
    }
}

// ---------------- launch ----------------
extern "C" void kernel_launch(void* const* d_in, const int* in_sizes, int n_in,
                              void* d_out, int out_size)
{
    const float* x           = (const float*)d_in[0];
    const float* ln1_w       = (const float*)d_in[1];
    const float* ln1_b       = (const float*)d_in[2];
    const float* W_attn      = (const float*)d_in[3];
    const float* b_attn      = (const float*)d_in[4];
    const float* W_attn_proj = (const float*)d_in[5];
    const float* b_attn_proj = (const float*)d_in[6];
    const float* ln2_w       = (const float*)d_in[7];
    const float* ln2_b       = (const float*)d_in[8];
    const float* W_fc        = (const float*)d_in[9];
    const float* b_fc        = (const float*)d_in[10];
    const float* W_mlp_proj  = (const float*)d_in[11];
    const float* b_mlp_proj  = (const float*)d_in[12];
    float* out = (float*)d_out;

    f16 *p_lnh, *p_qkvh, *p_qkvl, *p_atth, *p_fch;
    f16 *p_wah, *p_wph, *p_wfh, *p_wmh;
    float *p_x1;
    cudaGetSymbolAddress((void**)&p_lnh,  g_lnh);
    cudaGetSymbolAddress((void**)&p_qkvh, g_qkvh);
    cudaGetSymbolAddress((void**)&p_qkvl, g_qkvl);
    cudaGetSymbolAddress((void**)&p_atth, g_atth);
    cudaGetSymbolAddress((void**)&p_x1,   g_x1);
    cudaGetSymbolAddress((void**)&p_fch,  g_fch);
    cudaGetSymbolAddress((void**)&p_wah,  g_wah);
    cudaGetSymbolAddress((void**)&p_wph,  g_wph);
    cudaGetSymbolAddress((void**)&p_wfh,  g_wfh);
    cudaGetSymbolAddress((void**)&p_wmh,  g_wmh);

    cvt_kernel<<<(CDIM * QKVDIM / 8 + 255) / 256, 256>>>(W_attn,      p_wah, CDIM * QKVDIM / 8);
    cvt_kernel<<<(CDIM * CDIM   / 8 + 255) / 256, 256>>>(W_attn_proj, p_wph, CDIM * CDIM / 8);
    cvt_kernel<<<(CDIM * FCDIM  / 8 + 255) / 256, 256>>>(W_fc,        p_wfh, CDIM * FCDIM / 8);
    cvt_kernel<<<(FCDIM * CDIM  / 8 + 255) / 256, 256>>>(W_mlp_proj,  p_wmh, FCDIM * CDIM / 8);

    ln_kernel<<<MROWS, 256>>>(x, ln1_w, ln1_b, p_lnh);

    hgemm<3><<<dim3(QKVDIM / 128, MROWS / 128), 256>>>(p_lnh, p_wah,
        b_attn, (const float*)0, (float*)0, p_qkvh, p_qkvl, MROWS, QKVDIM, CDIM);

    fattn_kernel<<<dim3(SEQ / 64, NHEAD, BATCH), 128>>>(p_qkvh, p_qkvl, p_atth);

    hgemm<2><<<dim3(CDIM / 128, MROWS / 128), 256>>>(p_atth, p_wph,
        b_attn_proj, x, p_x1, (f16*)0, (f16*)0, MROWS, CDIM, CDIM);

    ln_kernel<<<MROWS, 256>>>(p_x1, ln2_w, ln2_b, p_lnh);

    hgemm<1><<<dim3(FCDIM / 128, MROWS / 128), 256>>>(p_lnh, p_wfh,
        b_fc, (const float*)0, (float*)0, p_fch, (f16*)0, MROWS, FCDIM, CDIM);

    hgemm<2><<<dim3(CDIM / 128, MROWS / 128), 256>>>(p_fch, p_wmh,
        b_mlp_proj, p_x1, out, (f16*)0, (f16*)0, MROWS, CDIM, FCDIM);
}

// round 9
// speedup vs baseline: 6.0336x; 1.0212x over previous
#include <cuda_runtime.h>
#include <cuda_fp16.h>
#include <stdint.h>
#include <math.h>

#define BATCH 4
#define SEQ   2048
#define CDIM  768
#define NHEAD 12
#define HDIM  64
#define MROWS 8192
#define QKVDIM 2304
#define FCDIM  3072

typedef __half f16;

// ---------------- device scratch ----------------
__device__ f16   g_lnh[MROWS*CDIM];
__device__ f16   g_qkvh[MROWS*QKVDIM];
__device__ f16   g_qkvl[MROWS*QKVDIM];
__device__ f16   g_atth[MROWS*CDIM];
__device__ float g_x1[MROWS*CDIM];
__device__ f16   g_fch[MROWS*FCDIM];
__device__ f16   g_wah[CDIM*QKVDIM];
__device__ f16   g_wph[CDIM*CDIM];
__device__ f16   g_wfh[CDIM*FCDIM];
__device__ f16   g_wmh[FCDIM*CDIM];

__device__ __forceinline__ void split_f16(float x, f16* h, f16* l)
{
    f16 hh = __float2half_rn(x);
    *h = hh;
    *l = __float2half_rn(x - __half2float(hh));
}

__device__ __forceinline__ uint32_t packh(float x, float y)
{
    __half2 t = __floats2half2_rn(x, y);
    return *(uint32_t*)&t;
}

// ---------------- cp.async helpers ----------------
__device__ __forceinline__ void cp16(void* s, const void* g)
{
    uint32_t a = (uint32_t)__cvta_generic_to_shared(s);
    asm volatile("cp.async.cg.shared.global [ %0 ], [ %1 ], 16;" :: "r"(a), "l"(g));
}

#define CP_COMMIT() asm volatile("cp.async.commit_group;")
#define CP_WAIT0()  asm volatile("cp.async.wait_group 0;")
#define CP_WAIT1()  asm volatile("cp.async.wait_group 1;")

// ---------------- fp32 -> fp16 weight conversion (8 elems/thread) ----------------
__global__ void cvt_kernel(const float* __restrict__ src, f16* __restrict__ hi, int n8)
{
    int i = blockIdx.x * 256 + threadIdx.x;
    if (i < n8) {
        float4 a = ((const float4*)src)[2 * i];
        float4 b = ((const float4*)src)[2 * i + 1];
        __half2 h0 = __floats2half2_rn(a.x, a.y);
        __half2 h1 = __floats2half2_rn(a.z, a.w);
        __half2 h2 = __floats2half2_rn(b.x, b.y);
        __half2 h3 = __floats2half2_rn(b.z, b.w);
        uint4 o;
        o.x = *(uint32_t*)&h0;
        o.y = *(uint32_t*)&h1;
        o.z = *(uint32_t*)&h2;
        o.w = *(uint32_t*)&h3;
        ((uint4*)hi)[i] = o;
    }
}

// ---------------- LayerNorm (fp16 hi output only) ----------------
__global__ __launch_bounds__(256) void ln_kernel(
    const float* __restrict__ x, const float* __restrict__ gw,
    const float* __restrict__ gb, f16* __restrict__ oh)
{
    __shared__ float ss[8];
    __shared__ float ss2[8];
    int row = blockIdx.x;
    const float* xr = x + (size_t)row * CDIM;
    float s = 0.f, s2 = 0.f;
    for (int i = threadIdx.x; i < CDIM; i += 256) {
        float t = xr[i];
        s += t;
        s2 += t * t;
    }
    for (int o = 16; o > 0; o >>= 1) {
        s  += __shfl_xor_sync(0xFFFFFFFFu, s,  o);
        s2 += __shfl_xor_sync(0xFFFFFFFFu, s2, o);
    }
    int wid = threadIdx.x >> 5;
    int lane = threadIdx.x & 31;
    if (lane == 0) {
        ss[wid] = s;
        ss2[wid] = s2;
    }
    __syncthreads();
    if (threadIdx.x == 0) {
        float a = 0.f, a2 = 0.f;
        for (int i = 0; i < 8; i++) {
            a += ss[i];
            a2 += ss2[i];
        }
        ss[0] = a;
        ss2[0] = a2;
    }
    __syncthreads();
    float mean = ss[0] * (1.f / CDIM);
    float var  = ss2[0] * (1.f / CDIM) - mean * mean;
    if (var < 0.f) var = 0.f;
    float inv = 1.f / (sqrtf(var) + 1e-6f);
    for (int i = threadIdx.x; i < CDIM; i += 256) {
        float v = gw[i] * (xr[i] - mean) * inv + gb[i];
        oh[(size_t)row * CDIM + i] = __float2half_rn(v);
    }
}

// ---------------- mma helpers (asm operand lists spaced) ----------------
__device__ __forceinline__ void ldsm_x4(uint32_t* r, const void* p)
{
    uint32_t addr = (uint32_t)__cvta_generic_to_shared(p);
    asm volatile("ldmatrix.sync.aligned.m8n8.x4.shared.b16 { %0, %1, %2, %3 }, [ %4 ];"
        : "=r"(r[0]), "=r"(r[1]), "=r"(r[2]), "=r"(r[3]) : "r"(addr));
}

__device__ __forceinline__ void ldsm_x4_t(uint32_t* r, const void* p)
{
    uint32_t addr = (uint32_t)__cvta_generic_to_shared(p);
    asm volatile("ldmatrix.sync.aligned.m8n8.x4.trans.shared.b16 { %0, %1, %2, %3 }, [ %4 ];"
        : "=r"(r[0]), "=r"(r[1]), "=r"(r[2]), "=r"(r[3]) : "r"(addr));
}

__device__ __forceinline__ void mma_f16(float* c, const uint32_t* a,
                                        uint32_t b0, uint32_t b1)
{
    asm volatile("mma.sync.aligned.m16n8k16.row.col.f32.f16.f16.f32 "
        "{ %0, %1, %2, %3 }, { %4, %5, %6, %7 }, { %8, %9 }, { %0, %1, %2, %3 };"
        : "+f"(c[0]), "+f"(c[1]), "+f"(c[2]), "+f"(c[3])
        : "r"(a[0]), "r"(a[1]), "r"(a[2]), "r"(a[3]), "r"(b0), "r"(b1));
}

// ---------------- 1-phase fp16 tensor-core GEMM, 3-stage cp.async ----------------
// C = A_hi @ B_hi + bias (+epilogue). fp32 accumulate.
// EPI: 1 = bias + GELU -> f16 hi
//      2 = bias + residual -> fp32
//      3 = bias -> f16 hi (+ lo plane for columns < CDIM, i.e. Q)
#define HG_SMEM_BYTES (3 * (128 * 40 + 32 * 136) * 2)

#define HG_LOAD(s_, kk_) \
    cp16(&As[s_][rA0][cA0], Ahi + (size_t)(row0 + rA0) * K + (kk_) + cA0); \
    cp16(&As[s_][rA1][cA0], Ahi + (size_t)(row0 + rA1) * K + (kk_) + cA0); \
    cp16(&Bs[s_][rB0][cB0], Bhi + (size_t)((kk_) + rB0) * N + col0 + cB0); \
    cp16(&Bs[s_][rB1][cB0], Bhi + (size_t)((kk_) + rB1) * N + col0 + cB0); \
    CP_COMMIT()

template<int EPI>
__global__ __launch_bounds__(256, 2) void hgemm(
    const f16* __restrict__ Ahi,
    const f16* __restrict__ Bhi,
    const float* __restrict__ bias, const float* __restrict__ res,
    float* __restrict__ Cf, f16* __restrict__ Chi, f16* __restrict__ Clo,
    int M, int N, int K)
{
    extern __shared__ f16 dsm[];
    f16 (*As)[128][40] = reinterpret_cast<f16 (*)[128][40]>(dsm);
    f16 (*Bs)[32][136] = reinterpret_cast<f16 (*)[32][136]>(dsm + 3 * 128 * 40);

    const int tid  = threadIdx.x;
    const int lane = tid & 31;
    const int warp = tid >> 5;
    const int wm = (warp >> 1) * 32;
    const int wn = (warp & 1) * 64;
    const int row0 = blockIdx.y * 128;
    const int col0 = blockIdx.x * 128;

    const int rA0 = tid >> 2;
    const int cA0 = (tid & 3) * 8;
    const int rA1 = rA0 + 64;
    const int rB0 = tid >> 4;
    const int cB0 = (tid & 15) * 8;
    const int rB1 = rB0 + 16;

    const int KT = K / 32;

    float acc[2][8][4];
    #pragma unroll
    for (int i = 0; i < 2; i++) {
        #pragma unroll
        for (int j = 0; j < 8; j++) {
            #pragma unroll
            for (int e = 0; e < 4; e++) {
                acc[i][j][e] = 0.f;
            }
        }
    }

    HG_LOAD(0, 0);
    HG_LOAD(1, 32);

    for (int it = 0; it < KT; ++it) {
        if (it + 1 < KT) {
            CP_WAIT1();
        } else {
            CP_WAIT0();
        }
        __syncthreads();
        if (it + 2 < KT) {
            HG_LOAD((it + 2) % 3, (it + 2) * 32);
        }
        const int s = it % 3;

        #pragma unroll
        for (int ks = 0; ks < 2; ++ks) {
            const int k0 = ks * 16;
            uint32_t af0[4];
            uint32_t af1[4];
            ldsm_x4(af0, &As[s][wm + (lane & 15)][k0 + (lane >> 4) * 8]);
            ldsm_x4(af1, &As[s][wm + 16 + (lane & 15)][k0 + (lane >> 4) * 8]);
            #pragma unroll
            for (int ni = 0; ni < 4; ++ni) {
                uint32_t bb[4];
                ldsm_x4_t(bb, &Bs[s][k0 + (lane & 15)][wn + ni * 16 + (lane >> 4) * 8]);
                mma_f16(acc[0][ni * 2 + 0], af0, bb[0], bb[1]);
                mma_f16(acc[0][ni * 2 + 1], af0, bb[2], bb[3]);
                mma_f16(acc[1][ni * 2 + 0], af1, bb[0], bb[1]);
                mma_f16(acc[1][ni * 2 + 1], af1, bb[2], bb[3]);
            }
        }
    }

    #pragma unroll
    for (int mi = 0; mi < 2; ++mi) {
        #pragma unroll
        for (int n8 = 0; n8 < 8; ++n8) {
            #pragma unroll
            for (int e = 0; e < 4; ++e) {
                int r = row0 + wm + mi * 16 + (lane >> 2) + (e >> 1) * 8;
                int c = col0 + wn + n8 * 8 + (lane & 3) * 2 + (e & 1);
                float v = acc[mi][n8][e] + bias[c];
                size_t off = (size_t)r * N + c;
                if (EPI == 1) {
                    v = 0.5f * v * (1.f + erff(v * 0.7071067811865475f));
                    Chi[off] = __float2half_rn(v);
                } else if (EPI == 3) {
                    if (c < CDIM) {
                        split_f16(v, Chi + off, Clo + off);
                    } else {
                        Chi[off] = __float2half_rn(v);
                    }
                } else {
                    Cf[off] = v + res[off];
                }
            }
        }
    }
}

// ---------------- Tensor-core flash attention (causal, fp16) ----------------
// grid: (SEQ/64, NHEAD, BATCH), 128 threads = 4 warps; warp owns 16 query rows.
// K/V tiles double-buffered via cp.async; longest CTAs launch first.
#define ATT_LOAD(s_, kt_) \
    _Pragma("unroll") \
    for (int li = 0; li < 4; li++) { \
        int e2 = tid + li * 128; \
        int r2 = e2 >> 3; \
        int c2 = (e2 & 7) * 8; \
        size_t goff2 = base + (size_t)((kt_) * 64 + r2) * QKVDIM + CDIM + h * HDIM + c2; \
        cp16(&KsH[s_][r2][c2], qkvh + goff2); \
        cp16(&Vs[s_][r2][c2], qkvh + goff2 + CDIM); \
    } \
    CP_COMMIT()

__global__ __launch_bounds__(128) void fattn_kernel(
    const f16* __restrict__ qkvh, const f16* __restrict__ qkvl,
    f16* __restrict__ outh)
{
    __shared__ f16 Qs[64][72];
    __shared__ f16 KsH[2][64][72];
    __shared__ f16 Vs[2][64][72];

    const int b = blockIdx.z;
    const int h = blockIdx.y;
    const int qb = (SEQ / 64 - 1) - blockIdx.x;   // longest first
    const int tid = threadIdx.x;
    const int lane = tid & 31;
    const int warp = tid >> 5;
    const int row0 = qb * 64;

    const size_t base = (size_t)b * SEQ * QKVDIM;
    const __half2 sc2 = __floats2half2_rn(0.125f, 0.125f);

    // kick off first K/V tile load immediately
    ATT_LOAD(0, 0);

    // ---- stage Q (hi), extract frags (scaled), then lo ----
    #pragma unroll
    for (int i = 0; i < 4; i++) {
        int e = tid + i * 128;
        int r = e >> 3;
        int c = (e & 7) * 8;
        *(uint4*)&Qs[r][c] = *(const uint4*)(qkvh + base + (size_t)(row0 + r) * QKVDIM + h * HDIM + c);
    }
    __syncthreads();
    uint32_t qh[4][4];
    uint32_t ql[4][4];
    #pragma unroll
    for (int kf = 0; kf < 4; kf++) {
        ldsm_x4(qh[kf], &Qs[warp * 16 + (lane & 15)][kf * 16 + (lane >> 4) * 8]);
        #pragma unroll
        for (int e = 0; e < 4; e++) {
            __half2 t = *(__half2*)&qh[kf][e];
            t = __hmul2(t, sc2);
            qh[kf][e] = *(uint32_t*)&t;
        }
    }
    __syncthreads();
    #pragma unroll
    for (int i = 0; i < 4; i++) {
        int e = tid + i * 128;
        int r = e >> 3;
        int c = (e & 7) * 8;
        *(uint4*)&Qs[r][c] = *(const uint4*)(qkvl + base + (size_t)(row0 + r) * QKVDIM + h * HDIM + c);
    }
    __syncthreads();
    #pragma unroll
    for (int kf = 0; kf < 4; kf++) {
        ldsm_x4(ql[kf], &Qs[warp * 16 + (lane & 15)][kf * 16 + (lane >> 4) * 8]);
        #pragma unroll
        for (int e = 0; e < 4; e++) {
            __half2 t = *(__half2*)&ql[kf][e];
            t = __hmul2(t, sc2);
            ql[kf][e] = *(uint32_t*)&t;
        }
    }

    float oacc[8][4];
    #pragma unroll
    for (int nb = 0; nb < 8; nb++) {
        #pragma unroll
        for (int e = 0; e < 4; e++) {
            oacc[nb][e] = 0.f;
        }
    }
    float m1 = -1e30f, m2 = -1e30f;
    float l1 = 0.f, l2 = 0.f;

    const int r1g = row0 + warp * 16 + (lane >> 2);
    const int r2g = r1g + 8;

    for (int kt = 0; kt <= qb; kt++) {
        const int j0g = kt * 64;
        CP_WAIT0();
        __syncthreads();
        if (kt + 1 <= qb) {
            ATT_LOAD((kt + 1) & 1, kt + 1);
        }
        const int s = kt & 1;

        // ---- S = Q K^T (2 phases, scale pre-folded) ----
        float sacc[8][4];
        #pragma unroll
        for (int nb = 0; nb < 8; nb++) {
            #pragma unroll
            for (int e = 0; e < 4; e++) {
                sacc[nb][e] = 0.f;
            }
        }
        #pragma unroll
        for (int kf = 0; kf < 4; kf++) {
            const int d0 = kf * 16;
            #pragma unroll
            for (int p = 0; p < 4; p++) {
                const int j0 = p * 16;
                uint32_t bh[4];
                ldsm_x4(bh, &KsH[s][j0 + ((lane >> 4) << 3) + (lane & 7)][d0 + (((lane >> 3) & 1) << 3)]);
                mma_f16(sacc[p * 2 + 0], qh[kf], bh[0], bh[1]);
                mma_f16(sacc[p * 2 + 1], qh[kf], bh[2], bh[3]);
                mma_f16(sacc[p * 2 + 0], ql[kf], bh[0], bh[1]);
                mma_f16(sacc[p * 2 + 1], ql[kf], bh[2], bh[3]);
            }
        }

        // ---- causal mask (diagonal tile only) ----
        if (kt == qb) {
            #pragma unroll
            for (int nb = 0; nb < 8; nb++) {
                int jg = j0g + nb * 8 + (lane & 3) * 2;
                if (jg     > r1g) sacc[nb][0] = -1e30f;
                if (jg + 1 > r1g) sacc[nb][1] = -1e30f;
                if (jg     > r2g) sacc[nb][2] = -1e30f;
                if (jg + 1 > r2g) sacc[nb][3] = -1e30f;
            }
        }

        // ---- online softmax ----
        float mx1 = -1e30f, mx2 = -1e30f;
        #pragma unroll
        for (int nb = 0; nb < 8; nb++) {
            mx1 = fmaxf(mx1, fmaxf(sacc[nb][0], sacc[nb][1]));
            mx2 = fmaxf(mx2, fmaxf(sacc[nb][2], sacc[nb][3]));
        }
        mx1 = fmaxf(mx1, __shfl_xor_sync(0xFFFFFFFFu, mx1, 1));
        mx1 = fmaxf(mx1, __shfl_xor_sync(0xFFFFFFFFu, mx1, 2));
        mx2 = fmaxf(mx2, __shfl_xor_sync(0xFFFFFFFFu, mx2, 1));
        mx2 = fmaxf(mx2, __shfl_xor_sync(0xFFFFFFFFu, mx2, 2));

        float nm1 = fmaxf(m1, mx1);
        float nm2 = fmaxf(m2, mx2);
        float co1 = __expf(m1 - nm1);
        float co2 = __expf(m2 - nm2);
        m1 = nm1;
        m2 = nm2;

        uint32_t pa1[8];
        uint32_t pa2[8];
        float ps1 = 0.f, ps2 = 0.f;
        #pragma unroll
        for (int nb = 0; nb < 8; nb++) {
            float p0 = __expf(sacc[nb][0] - m1);
            float p1 = __expf(sacc[nb][1] - m1);
            float p2 = __expf(sacc[nb][2] - m2);
            float p3 = __expf(sacc[nb][3] - m2);
            ps1 += p0 + p1;
            ps2 += p2 + p3;
            pa1[nb] = packh(p0, p1);
            pa2[nb] = packh(p2, p3);
        }
        l1 = l1 * co1 + ps1;
        l2 = l2 * co2 + ps2;
        #pragma unroll
        for (int nb = 0; nb < 8; nb++) {
            oacc[nb][0] *= co1;
            oacc[nb][1] *= co1;
            oacc[nb][2] *= co2;
            oacc[nb][3] *= co2;
        }

        // ---- O += P V ----
        #pragma unroll
        for (int kf = 0; kf < 4; kf++) {
            uint32_t af[4];
            af[0] = pa1[kf * 2];
            af[1] = pa2[kf * 2];
            af[2] = pa1[kf * 2 + 1];
            af[3] = pa2[kf * 2 + 1];
            #pragma unroll
            for (int pd = 0; pd < 4; pd++) {
                uint32_t bb[4];
                ldsm_x4_t(bb, &Vs[s][kf * 16 + (lane & 15)][pd * 16 + (lane >> 4) * 8]);
                mma_f16(oacc[pd * 2 + 0], af, bb[0], bb[1]);
                mma_f16(oacc[pd * 2 + 1], af, bb[2], bb[3]);
            }
        }
    }

    // ---- finalize ----
    l1 += __shfl_xor_sync(0xFFFFFFFFu, l1, 1);
    l1 += __shfl_xor_sync(0xFFFFFFFFu, l1, 2);
    l2 += __shfl_xor_sync(0xFFFFFFFFu, l2, 1);
    l2 += __shfl_xor_sync(0xFFFFFFFFu, l2, 2);
    float inv1 = 1.f / l1;
    float inv2 = 1.f / l2;

    size_t ob1 = (size_t)(b * SEQ + r1g) * CDIM + h * HDIM;
    size_t ob2 = (size_t)(b * SEQ + r2g) * CDIM + h * HDIM;
    #pragma unroll
    for (int nb = 0; nb < 8; nb++) {
        int c = nb * 8 + (lane & 3) * 2;
        outh[ob1 + c    ] = __float2half_rn(oacc[nb][0] * inv1);
        outh[ob1 + c + 1] = __float2half_rn(oacc[nb][1] * inv1);
        outh[ob2 + c    ] = __float2half_rn(oacc[nb][2] * inv2);
        outh[ob2 + c + 1] = __float2half_rn(oacc[nb][3] * inv2);
    }
}

// ---------------- launch ----------------
extern "C" void kernel_launch(void* const* d_in, const int* in_sizes, int n_in,
                              void* d_out, int out_size)
{
    const float* x           = (const float*)d_in[0];
    const float* ln1_w       = (const float*)d_in[1];
    const float* ln1_b       = (const float*)d_in[2];
    const float* W_attn      = (const float*)d_in[3];
    const float* b_attn      = (const float*)d_in[4];
    const float* W_attn_proj = (const float*)d_in[5];
    const float* b_attn_proj = (const float*)d_in[6];
    const float* ln2_w       = (const float*)d_in[7];
    const float* ln2_b       = (const float*)d_in[8];
    const float* W_fc        = (const float*)d_in[9];
    const float* b_fc        = (const float*)d_in[10];
    const float* W_mlp_proj  = (const float*)d_in[11];
    const float* b_mlp_proj  = (const float*)d_in[12];
    float* out = (float*)d_out;

    f16 *p_lnh, *p_qkvh, *p_qkvl, *p_atth, *p_fch;
    f16 *p_wah, *p_wph, *p_wfh, *p_wmh;
    float *p_x1;
    cudaGetSymbolAddress((void**)&p_lnh,  g_lnh);
    cudaGetSymbolAddress((void**)&p_qkvh, g_qkvh);
    cudaGetSymbolAddress((void**)&p_qkvl, g_qkvl);
    cudaGetSymbolAddress((void**)&p_atth, g_atth);
    cudaGetSymbolAddress((void**)&p_x1,   g_x1);
    cudaGetSymbolAddress((void**)&p_fch,  g_fch);
    cudaGetSymbolAddress((void**)&p_wah,  g_wah);
    cudaGetSymbolAddress((void**)&p_wph,  g_wph);
    cudaGetSymbolAddress((void**)&p_wfh,  g_wfh);
    cudaGetSymbolAddress((void**)&p_wmh,  g_wmh);

    cudaFuncSetAttribute(hgemm<1>, cudaFuncAttributeMaxDynamicSharedMemorySize, HG_SMEM_BYTES);
    cudaFuncSetAttribute(hgemm<2>, cudaFuncAttributeMaxDynamicSharedMemorySize, HG_SMEM_BYTES);
    cudaFuncSetAttribute(hgemm<3>, cudaFuncAttributeMaxDynamicSharedMemorySize, HG_SMEM_BYTES);

    cvt_kernel<<<(CDIM * QKVDIM / 8 + 255) / 256, 256>>>(W_attn,      p_wah, CDIM * QKVDIM / 8);
    cvt_kernel<<<(CDIM * CDIM   / 8 + 255) / 256, 256>>>(W_attn_proj, p_wph, CDIM * CDIM / 8);
    cvt_kernel<<<(CDIM * FCDIM  / 8 + 255) / 256, 256>>>(W_fc,        p_wfh, CDIM * FCDIM / 8);
    cvt_kernel<<<(FCDIM * CDIM  / 8 + 255) / 256, 256>>>(W_mlp_proj,  p_wmh, FCDIM * CDIM / 8);

    ln_kernel<<<MROWS, 256>>>(x, ln1_w, ln1_b, p_lnh);

    hgemm<3><<<dim3(QKVDIM / 128, MROWS / 128), 256, HG_SMEM_BYTES>>>(p_lnh, p_wah,
        b_attn, (const float*)0, (float*)0, p_qkvh, p_qkvl, MROWS, QKVDIM, CDIM);

    fattn_kernel<<<dim3(SEQ / 64, NHEAD, BATCH), 128>>>(p_qkvh, p_qkvl, p_atth);

    hgemm<2><<<dim3(CDIM / 128, MROWS / 128), 256, HG_SMEM_BYTES>>>(p_atth, p_wph,
        b_attn_proj, x, p_x1, (f16*)0, (f16*)0, MROWS, CDIM, CDIM);

    ln_kernel<<<MROWS, 256>>>(p_x1, ln2_w, ln2_b, p_lnh);

    hgemm<1><<<dim3(FCDIM / 128, MROWS / 128), 256, HG_SMEM_BYTES>>>(p_lnh, p_wfh,
        b_fc, (const float*)0, (float*)0, p_fch, (f16*)0, MROWS, FCDIM, CDIM);

    hgemm<2><<<dim3(CDIM / 128, MROWS / 128), 256, HG_SMEM_BYTES>>>(p_fch, p_wmh,
        b_mlp_proj, p_x1, out, (f16*)0, (f16*)0, MROWS, CDIM, FCDIM);
}

// round 11
// speedup vs baseline: 6.4495x; 1.0689x over previous
#include <cuda_runtime.h>
#include <cuda_fp16.h>
#include <stdint.h>
#include <math.h>

#define BATCH 4
#define SEQ   2048
#define CDIM  768
#define NHEAD 12
#define HDIM  64
#define MROWS 8192
#define QKVDIM 2304
#define FCDIM  3072

typedef __half f16;

// ---------------- device scratch ----------------
__device__ f16   g_lnh[MROWS*CDIM];
__device__ f16   g_qkvh[MROWS*QKVDIM];
__device__ f16   g_atth[MROWS*CDIM];
__device__ float g_x1[MROWS*CDIM];
__device__ f16   g_fch[MROWS*FCDIM];
__device__ f16   g_wah[CDIM*QKVDIM];
__device__ f16   g_wph[CDIM*CDIM];
__device__ f16   g_wfh[CDIM*FCDIM];
__device__ f16   g_wmh[FCDIM*CDIM];

__device__ __forceinline__ uint32_t packh(float x, float y)
{
    __half2 t = __floats2half2_rn(x, y);
    return *(uint32_t*)&t;
}

// ---------------- cp.async helpers ----------------
__device__ __forceinline__ void cp16(void* s, const void* g)
{
    uint32_t a = (uint32_t)__cvta_generic_to_shared(s);
    asm volatile("cp.async.cg.shared.global [ %0 ], [ %1 ], 16;" :: "r"(a), "l"(g));
}

#define CP_COMMIT() asm volatile("cp.async.commit_group;")
#define CP_WAIT0()  asm volatile("cp.async.wait_group 0;")
#define CP_WAIT1()  asm volatile("cp.async.wait_group 1;")

// ---------------- fp32 -> fp16 weight conversion (8 elems/thread) ----------------
__global__ void cvt_kernel(const float* __restrict__ src, f16* __restrict__ hi, int n8)
{
    int i = blockIdx.x * 256 + threadIdx.x;
    if (i < n8) {
        float4 a = ((const float4*)src)[2 * i];
        float4 b = ((const float4*)src)[2 * i + 1];
        __half2 h0 = __floats2half2_rn(a.x, a.y);
        __half2 h1 = __floats2half2_rn(a.z, a.w);
        __half2 h2 = __floats2half2_rn(b.x, b.y);
        __half2 h3 = __floats2half2_rn(b.z, b.w);
        uint4 o;
        o.x = *(uint32_t*)&h0;
        o.y = *(uint32_t*)&h1;
        o.z = *(uint32_t*)&h2;
        o.w = *(uint32_t*)&h3;
        ((uint4*)hi)[i] = o;
    }
}

// ---------------- LayerNorm (fp16 output) ----------------
__global__ __launch_bounds__(256) void ln_kernel(
    const float* __restrict__ x, const float* __restrict__ gw,
    const float* __restrict__ gb, f16* __restrict__ oh)
{
    __shared__ float ss[8];
    __shared__ float ss2[8];
    int row = blockIdx.x;
    const float* xr = x + (size_t)row * CDIM;
    float s = 0.f, s2 = 0.f;
    for (int i = threadIdx.x; i < CDIM; i += 256) {
        float t = xr[i];
        s += t;
        s2 += t * t;
    }
    for (int o = 16; o > 0; o >>= 1) {
        s  += __shfl_xor_sync(0xFFFFFFFFu, s,  o);
        s2 += __shfl_xor_sync(0xFFFFFFFFu, s2, o);
    }
    int wid = threadIdx.x >> 5;
    int lane = threadIdx.x & 31;
    if (lane == 0) {
        ss[wid] = s;
        ss2[wid] = s2;
    }
    __syncthreads();
    if (threadIdx.x == 0) {
        float a = 0.f, a2 = 0.f;
        for (int i = 0; i < 8; i++) {
            a += ss[i];
            a2 += ss2[i];
        }
        ss[0] = a;
        ss2[0] = a2;
    }
    __syncthreads();
    float mean = ss[0] * (1.f / CDIM);
    float var  = ss2[0] * (1.f / CDIM) - mean * mean;
    if (var < 0.f) var = 0.f;
    float inv = 1.f / (sqrtf(var) + 1e-6f);
    for (int i = threadIdx.x; i < CDIM; i += 256) {
        float v = gw[i] * (xr[i] - mean) * inv + gb[i];
        oh[(size_t)row * CDIM + i] = __float2half_rn(v);
    }
}

// ---------------- mma helpers (asm operand lists spaced) ----------------
__device__ __forceinline__ void ldsm_x4(uint32_t* r, const void* p)
{
    uint32_t addr = (uint32_t)__cvta_generic_to_shared(p);
    asm volatile("ldmatrix.sync.aligned.m8n8.x4.shared.b16 { %0, %1, %2, %3 }, [ %4 ];"
        : "=r"(r[0]), "=r"(r[1]), "=r"(r[2]), "=r"(r[3]) : "r"(addr));
}

__device__ __forceinline__ void ldsm_x4_t(uint32_t* r, const void* p)
{
    uint32_t addr = (uint32_t)__cvta_generic_to_shared(p);
    asm volatile("ldmatrix.sync.aligned.m8n8.x4.trans.shared.b16 { %0, %1, %2, %3 }, [ %4 ];"
        : "=r"(r[0]), "=r"(r[1]), "=r"(r[2]), "=r"(r[3]) : "r"(addr));
}

__device__ __forceinline__ void mma_f16(float* c, const uint32_t* a,
                                        uint32_t b0, uint32_t b1)
{
    asm volatile("mma.sync.aligned.m16n8k16.row.col.f32.f16.f16.f32 "
        "{ %0, %1, %2, %3 }, { %4, %5, %6, %7 }, { %8, %9 }, { %0, %1, %2, %3 };"
        : "+f"(c[0]), "+f"(c[1]), "+f"(c[2]), "+f"(c[3])
        : "r"(a[0]), "r"(a[1]), "r"(a[2]), "r"(a[3]), "r"(b0), "r"(b1));
}

// ---------------- 1-phase fp16 tensor-core GEMM, 3-stage cp.async ----------------
// C = A_hi @ B_hi + bias (+epilogue). fp32 accumulate.
// EPI: 1 = bias + GELU -> f16
//      2 = bias + residual -> fp32
//      3 = bias -> f16
#define HG_SMEM_BYTES (3 * (128 * 40 + 32 * 136) * 2)

#define HG_LOAD(s_, kk_) \
    cp16(&As[s_][rA0][cA0], Ahi + (size_t)(row0 + rA0) * K + (kk_) + cA0); \
    cp16(&As[s_][rA1][cA0], Ahi + (size_t)(row0 + rA1) * K + (kk_) + cA0); \
    cp16(&Bs[s_][rB0][cB0], Bhi + (size_t)((kk_) + rB0) * N + col0 + cB0); \
    cp16(&Bs[s_][rB1][cB0], Bhi + (size_t)((kk_) + rB1) * N + col0 + cB0); \
    CP_COMMIT()

template<int EPI>
__global__ __launch_bounds__(256, 2) void hgemm(
    const f16* __restrict__ Ahi,
    const f16* __restrict__ Bhi,
    const float* __restrict__ bias, const float* __restrict__ res,
    float* __restrict__ Cf, f16* __restrict__ Chi,
    int M, int N, int K)
{
    extern __shared__ f16 dsm[];
    f16 (*As)[128][40] = reinterpret_cast<f16 (*)[128][40]>(dsm);
    f16 (*Bs)[32][136] = reinterpret_cast<f16 (*)[32][136]>(dsm + 3 * 128 * 40);

    const int tid  = threadIdx.x;
    const int lane = tid & 31;
    const int warp = tid >> 5;
    const int wm = (warp >> 1) * 32;
    const int wn = (warp & 1) * 64;
    const int row0 = blockIdx.y * 128;
    const int col0 = blockIdx.x * 128;

    const int rA0 = tid >> 2;
    const int cA0 = (tid & 3) * 8;
    const int rA1 = rA0 + 64;
    const int rB0 = tid >> 4;
    const int cB0 = (tid & 15) * 8;
    const int rB1 = rB0 + 16;

    const int KT = K / 32;

    float acc[2][8][4];
    #pragma unroll
    for (int i = 0; i < 2; i++) {
        #pragma unroll
        for (int j = 0; j < 8; j++) {
            #pragma unroll
            for (int e = 0; e < 4; e++) {
                acc[i][j][e] = 0.f;
            }
        }
    }

    HG_LOAD(0, 0);
    HG_LOAD(1, 32);

    for (int it = 0; it < KT; ++it) {
        if (it + 1 < KT) {
            CP_WAIT1();
        } else {
            CP_WAIT0();
        }
        __syncthreads();
        if (it + 2 < KT) {
            HG_LOAD((it + 2) % 3, (it + 2) * 32);
        }
        const int s = it % 3;

        #pragma unroll
        for (int ks = 0; ks < 2; ++ks) {
            const int k0 = ks * 16;
            uint32_t af0[4];
            uint32_t af1[4];
            ldsm_x4(af0, &As[s][wm + (lane & 15)][k0 + (lane >> 4) * 8]);
            ldsm_x4(af1, &As[s][wm + 16 + (lane & 15)][k0 + (lane >> 4) * 8]);
            #pragma unroll
            for (int ni = 0; ni < 4; ++ni) {
                uint32_t bb[4];
                ldsm_x4_t(bb, &Bs[s][k0 + (lane & 15)][wn + ni * 16 + (lane >> 4) * 8]);
                mma_f16(acc[0][ni * 2 + 0], af0, bb[0], bb[1]);
                mma_f16(acc[0][ni * 2 + 1], af0, bb[2], bb[3]);
                mma_f16(acc[1][ni * 2 + 0], af1, bb[0], bb[1]);
                mma_f16(acc[1][ni * 2 + 1], af1, bb[2], bb[3]);
            }
        }
    }

    #pragma unroll
    for (int mi = 0; mi < 2; ++mi) {
        #pragma unroll
        for (int n8 = 0; n8 < 8; ++n8) {
            #pragma unroll
            for (int e = 0; e < 4; ++e) {
                int r = row0 + wm + mi * 16 + (lane >> 2) + (e >> 1) * 8;
                int c = col0 + wn + n8 * 8 + (lane & 3) * 2 + (e & 1);
                float v = acc[mi][n8][e] + bias[c];
                size_t off = (size_t)r * N + c;
                if (EPI == 1) {
                    v = 0.5f * v * (1.f + erff(v * 0.7071067811865475f));
                    Chi[off] = __float2half_rn(v);
                } else if (EPI == 3) {
                    Chi[off] = __float2half_rn(v);
                } else {
                    Cf[off] = v + res[off];
                }
            }
        }
    }
}

// ---------------- Tensor-core flash attention (causal, fp16) ----------------
// grid: (SEQ/64, NHEAD, BATCH), 128 threads = 4 warps; warp owns 16 query rows.
// 1-phase fp16 QK^T (scale folded into Q frags); PV in fp16; fp32 softmax state.
// K/V tiles double-buffered via cp.async; longest CTAs launch first.
#define ATT_LOAD(s_, kt_) \
    _Pragma("unroll") \
    for (int li = 0; li < 4; li++) { \
        int e2 = tid + li * 128; \
        int r2 = e2 >> 3; \
        int c2 = (e2 & 7) * 8; \
        size_t goff2 = base + (size_t)((kt_) * 64 + r2) * QKVDIM + CDIM + h * HDIM + c2; \
        cp16(&KsH[s_][r2][c2], qkvh + goff2); \
        cp16(&Vs[s_][r2][c2], qkvh + goff2 + CDIM); \
    } \
    CP_COMMIT()

__global__ __launch_bounds__(128) void fattn_kernel(
    const f16* __restrict__ qkvh, f16* __restrict__ outh)
{
    __shared__ f16 Qs[64][72];
    __shared__ f16 KsH[2][64][72];
    __shared__ f16 Vs[2][64][72];

    const int b = blockIdx.z;
    const int h = blockIdx.y;
    const int qb = (SEQ / 64 - 1) - blockIdx.x;   // longest first
    const int tid = threadIdx.x;
    const int lane = tid & 31;
    const int warp = tid >> 5;
    const int row0 = qb * 64;

    const size_t base = (size_t)b * SEQ * QKVDIM;
    const __half2 sc2 = __floats2half2_rn(0.125f, 0.125f);

    // kick off first K/V tile load immediately
    ATT_LOAD(0, 0);

    // ---- stage Q, extract frags (scaled) ----
    #pragma unroll
    for (int i = 0; i < 4; i++) {
        int e = tid + i * 128;
        int r = e >> 3;
        int c = (e & 7) * 8;
        *(uint4*)&Qs[r][c] = *(const uint4*)(qkvh + base + (size_t)(row0 + r) * QKVDIM + h * HDIM + c);
    }
    __syncthreads();
    uint32_t qh[4][4];
    #pragma unroll
    for (int kf = 0; kf < 4; kf++) {
        ldsm_x4(qh[kf], &Qs[warp * 16 + (lane & 15)][kf * 16 + (lane >> 4) * 8]);
        #pragma unroll
        for (int e = 0; e < 4; e++) {
            __half2 t = *(__half2*)&qh[kf][e];
            t = __hmul2(t, sc2);
            qh[kf][e] = *(uint32_t*)&t;
        }
    }

    float oacc[8][4];
    #pragma unroll
    for (int nb = 0; nb < 8; nb++) {
        #pragma unroll
        for (int e = 0; e < 4; e++) {
            oacc[nb][e] = 0.f;
        }
    }
    float m1 = -1e30f, m2 = -1e30f;
    float l1 = 0.f, l2 = 0.f;

    const int r1g = row0 + warp * 16 + (lane >> 2);
    const int r2g = r1g + 8;

    for (int kt = 0; kt <= qb; kt++) {
        const int j0g = kt * 64;
        CP_WAIT0();
        __syncthreads();
        if (kt + 1 <= qb) {
            ATT_LOAD((kt + 1) & 1, kt + 1);
        }
        const int s = kt & 1;

        // ---- S = Q K^T (1 phase, scale pre-folded) ----
        float sacc[8][4];
        #pragma unroll
        for (int nb = 0; nb < 8; nb++) {
            #pragma unroll
            for (int e = 0; e < 4; e++) {
                sacc[nb][e] = 0.f;
            }
        }
        #pragma unroll
        for (int kf = 0; kf < 4; kf++) {
            const int d0 = kf * 16;
            #pragma unroll
            for (int p = 0; p < 4; p++) {
                const int j0 = p * 16;
                uint32_t bh[4];
                ldsm_x4(bh, &KsH[s][j0 + ((lane >> 4) << 3) + (lane & 7)][d0 + (((lane >> 3) & 1) << 3)]);
                mma_f16(sacc[p * 2 + 0], qh[kf], bh[0], bh[1]);
                mma_f16(sacc[p * 2 + 1], qh[kf], bh[2], bh[3]);
            }
        }

        // ---- causal mask (diagonal tile only) ----
        if (kt == qb) {
            #pragma unroll
            for (int nb = 0; nb < 8; nb++) {
                int jg = j0g + nb * 8 + (lane & 3) * 2;
                if (jg     > r1g) sacc[nb][0] = -1e30f;
                if (jg + 1 > r1g) sacc[nb][1] = -1e30f;
                if (jg     > r2g) sacc[nb][2] = -1e30f;
                if (jg + 1 > r2g) sacc[nb][3] = -1e30f;
            }
        }

        // ---- online softmax ----
        float mx1 = -1e30f, mx2 = -1e30f;
        #pragma unroll
        for (int nb = 0; nb < 8; nb++) {
            mx1 = fmaxf(mx1, fmaxf(sacc[nb][0], sacc[nb][1]));
            mx2 = fmaxf(mx2, fmaxf(sacc[nb][2], sacc[nb][3]));
        }
        mx1 = fmaxf(mx1, __shfl_xor_sync(0xFFFFFFFFu, mx1, 1));
        mx1 = fmaxf(mx1, __shfl_xor_sync(0xFFFFFFFFu, mx1, 2));
        mx2 = fmaxf(mx2, __shfl_xor_sync(0xFFFFFFFFu, mx2, 1));
        mx2 = fmaxf(mx2, __shfl_xor_sync(0xFFFFFFFFu, mx2, 2));

        float nm1 = fmaxf(m1, mx1);
        float nm2 = fmaxf(m2, mx2);
        float co1 = __expf(m1 - nm1);
        float co2 = __expf(m2 - nm2);
        m1 = nm1;
        m2 = nm2;

        uint32_t pa1[8];
        uint32_t pa2[8];
        float ps1 = 0.f, ps2 = 0.f;
        #pragma unroll
        for (int nb = 0; nb < 8; nb++) {
            float p0 = __expf(sacc[nb][0] - m1);
            float p1 = __expf(sacc[nb][1] - m1);
            float p2 = __expf(sacc[nb][2] - m2);
            float p3 = __expf(sacc[nb][3] - m2);
            ps1 += p0 + p1;
            ps2 += p2 + p3;
            pa1[nb] = packh(p0, p1);
            pa2[nb] = packh(p2, p3);
        }
        l1 = l1 * co1 + ps1;
        l2 = l2 * co2 + ps2;
        #pragma unroll
        for (int nb = 0; nb < 8; nb++) {
            oacc[nb][0] *= co1;
            oacc[nb][1] *= co1;
            oacc[nb][2] *= co2;
            oacc[nb][3] *= co2;
        }

        // ---- O += P V ----
        #pragma unroll
        for (int kf = 0; kf < 4; kf++) {
            uint32_t af[4];
            af[0] = pa1[kf * 2];
            af[1] = pa2[kf * 2];
            af[2] = pa1[kf * 2 + 1];
            af[3] = pa2[kf * 2 + 1];
            #pragma unroll
            for (int pd = 0; pd < 4; pd++) {
                uint32_t bb[4];
                ldsm_x4_t(bb, &Vs[s][kf * 16 + (lane & 15)][pd * 16 + (lane >> 4) * 8]);
                mma_f16(oacc[pd * 2 + 0], af, bb[0], bb[1]);
                mma_f16(oacc[pd * 2 + 1], af, bb[2], bb[3]);
            }
        }
    }

    // ---- finalize ----
    l1 += __shfl_xor_sync(0xFFFFFFFFu, l1, 1);
    l1 += __shfl_xor_sync(0xFFFFFFFFu, l1, 2);
    l2 += __shfl_xor_sync(0xFFFFFFFFu, l2, 1);
    l2 += __shfl_xor_sync(0xFFFFFFFFu, l2, 2);
    float inv1 = 1.f / l1;
    float inv2 = 1.f / l2;

    size_t ob1 = (size_t)(b * SEQ + r1g) * CDIM + h * HDIM;
    size_t ob2 = (size_t)(b * SEQ + r2g) * CDIM + h * HDIM;
    #pragma unroll
    for (int nb = 0; nb < 8; nb++) {
        int c = nb * 8 + (lane & 3) * 2;
        outh[ob1 + c    ] = __float2half_rn(oacc[nb][0] * inv1);
        outh[ob1 + c + 1] = __float2half_rn(oacc[nb][1] * inv1);
        outh[ob2 + c    ] = __float2half_rn(oacc[nb][2] * inv2);
        outh[ob2 + c + 1] = __float2half_rn(oacc[nb][3] * inv2);
    }
}

// ---------------- launch ----------------
extern "C" void kernel_launch(void* const* d_in, const int* in_sizes, int n_in,
                              void* d_out, int out_size)
{
    const float* x           = (const float*)d_in[0];
    const float* ln1_w       = (const float*)d_in[1];
    const float* ln1_b       = (const float*)d_in[2];
    const float* W_attn      = (const float*)d_in[3];
    const float* b_attn      = (const float*)d_in[4];
    const float* W_attn_proj = (const float*)d_in[5];
    const float* b_attn_proj = (const float*)d_in[6];
    const float* ln2_w       = (const float*)d_in[7];
    const float* ln2_b       = (const float*)d_in[8];
    const float* W_fc        = (const float*)d_in[9];
    const float* b_fc        = (const float*)d_in[10];
    const float* W_mlp_proj  = (const float*)d_in[11];
    const float* b_mlp_proj  = (const float*)d_in[12];
    float* out = (float*)d_out;

    f16 *p_lnh, *p_qkvh, *p_atth, *p_fch;
    f16 *p_wah, *p_wph, *p_wfh, *p_wmh;
    float *p_x1;
    cudaGetSymbolAddress((void**)&p_lnh,  g_lnh);
    cudaGetSymbolAddress((void**)&p_qkvh, g_qkvh);
    cudaGetSymbolAddress((void**)&p_atth, g_atth);
    cudaGetSymbolAddress((void**)&p_x1,   g_x1);
    cudaGetSymbolAddress((void**)&p_fch,  g_fch);
    cudaGetSymbolAddress((void**)&p_wah,  g_wah);
    cudaGetSymbolAddress((void**)&p_wph,  g_wph);
    cudaGetSymbolAddress((void**)&p_wfh,  g_wfh);
    cudaGetSymbolAddress((void**)&p_wmh,  g_wmh);

    cudaFuncSetAttribute(hgemm<1>, cudaFuncAttributeMaxDynamicSharedMemorySize, HG_SMEM_BYTES);
    cudaFuncSetAttribute(hgemm<2>, cudaFuncAttributeMaxDynamicSharedMemorySize, HG_SMEM_BYTES);
    cudaFuncSetAttribute(hgemm<3>, cudaFuncAttributeMaxDynamicSharedMemorySize, HG_SMEM_BYTES);

    cvt_kernel<<<(CDIM * QKVDIM / 8 + 255) / 256, 256>>>(W_attn,      p_wah, CDIM * QKVDIM / 8);
    cvt_kernel<<<(CDIM * CDIM   / 8 + 255) / 256, 256>>>(W_attn_proj, p_wph, CDIM * CDIM / 8);
    cvt_kernel<<<(CDIM * FCDIM  / 8 + 255) / 256, 256>>>(W_fc,        p_wfh, CDIM * FCDIM / 8);
    cvt_kernel<<<(FCDIM * CDIM  / 8 + 255) / 256, 256>>>(W_mlp_proj,  p_wmh, FCDIM * CDIM / 8);

    ln_kernel<<<MROWS, 256>>>(x, ln1_w, ln1_b, p_lnh);

    hgemm<3><<<dim3(QKVDIM / 128, MROWS / 128), 256, HG_SMEM_BYTES>>>(p_lnh, p_wah,
        b_attn, (const float*)0, (float*)0, p_qkvh, MROWS, QKVDIM, CDIM);

    fattn_kernel<<<dim3(SEQ / 64, NHEAD, BATCH), 128>>>(p_qkvh, p_atth);

    hgemm<2><<<dim3(CDIM / 128, MROWS / 128), 256, HG_SMEM_BYTES>>>(p_atth, p_wph,
        b_attn_proj, x, p_x1, (f16*)0, MROWS, CDIM, CDIM);

    ln_kernel<<<MROWS, 256>>>(p_x1, ln2_w, ln2_b, p_lnh);

    hgemm<1><<<dim3(FCDIM / 128, MROWS / 128), 256, HG_SMEM_BYTES>>>(p_lnh, p_wfh,
        b_fc, (const float*)0, (float*)0, p_fch, MROWS, FCDIM, CDIM);

    hgemm<2><<<dim3(CDIM / 128, MROWS / 128), 256, HG_SMEM_BYTES>>>(p_fch, p_wmh,
        b_mlp_proj, p_x1, out, (f16*)0, MROWS, CDIM, FCDIM);
}

// round 12
// speedup vs baseline: 7.7182x; 1.1967x over previous
#include <cuda_runtime.h>
#include <cuda_fp16.h>
#include <stdint.h>
#include <math.h>

#define BATCH 4
#define SEQ   2048
#define CDIM  768
#define NHEAD 12
#define HDIM  64
#define MROWS 8192
#define QKVDIM 2304
#define FCDIM  3072

typedef __half f16;

// ---------------- device scratch ----------------
__device__ f16   g_lnh[MROWS*CDIM];
__device__ f16   g_qkvh[MROWS*QKVDIM];
__device__ f16   g_atth[MROWS*CDIM];
__device__ float g_x1[MROWS*CDIM];
__device__ f16   g_fch[MROWS*FCDIM];
__device__ f16   g_wah[CDIM*QKVDIM];
__device__ f16   g_wph[CDIM*CDIM];
__device__ f16   g_wfh[CDIM*FCDIM];
__device__ f16   g_wmh[FCDIM*CDIM];

__device__ __forceinline__ uint32_t packh(float x, float y)
{
    __half2 t = __floats2half2_rn(x, y);
    return *(uint32_t*)&t;
}

// ---------------- cp.async helpers ----------------
__device__ __forceinline__ void cp16(void* s, const void* g)
{
    uint32_t a = (uint32_t)__cvta_generic_to_shared(s);
    asm volatile("cp.async.cg.shared.global [ %0 ], [ %1 ], 16;" :: "r"(a), "l"(g));
}

#define CP_COMMIT() asm volatile("cp.async.commit_group;")
#define CP_WAIT0()  asm volatile("cp.async.wait_group 0;")
#define CP_WAIT1()  asm volatile("cp.async.wait_group 1;")

// ---------------- fp32 -> fp16 weight conversion (8 elems/thread) ----------------
__global__ void cvt_kernel(const float* __restrict__ src, f16* __restrict__ hi, int n8)
{
    int i = blockIdx.x * 256 + threadIdx.x;
    if (i < n8) {
        float4 a = ((const float4*)src)[2 * i];
        float4 b = ((const float4*)src)[2 * i + 1];
        __half2 h0 = __floats2half2_rn(a.x, a.y);
        __half2 h1 = __floats2half2_rn(a.z, a.w);
        __half2 h2 = __floats2half2_rn(b.x, b.y);
        __half2 h3 = __floats2half2_rn(b.z, b.w);
        uint4 o;
        o.x = *(uint32_t*)&h0;
        o.y = *(uint32_t*)&h1;
        o.z = *(uint32_t*)&h2;
        o.w = *(uint32_t*)&h3;
        ((uint4*)hi)[i] = o;
    }
}

// ---------------- LayerNorm (single global read, fp16 output) ----------------
__global__ __launch_bounds__(256) void ln_kernel(
    const float* __restrict__ x, const float* __restrict__ gw,
    const float* __restrict__ gb, f16* __restrict__ oh)
{
    __shared__ float ss[8];
    __shared__ float ss2[8];
    int row = blockIdx.x;
    const float* xr = x + (size_t)row * CDIM;
    float xv[3];
    float s = 0.f, s2 = 0.f;
    #pragma unroll
    for (int j = 0; j < 3; j++) {
        xv[j] = xr[threadIdx.x + j * 256];
        s += xv[j];
        s2 += xv[j] * xv[j];
    }
    for (int o = 16; o > 0; o >>= 1) {
        s  += __shfl_xor_sync(0xFFFFFFFFu, s,  o);
        s2 += __shfl_xor_sync(0xFFFFFFFFu, s2, o);
    }
    int wid = threadIdx.x >> 5;
    int lane = threadIdx.x & 31;
    if (lane == 0) {
        ss[wid] = s;
        ss2[wid] = s2;
    }
    __syncthreads();
    if (threadIdx.x == 0) {
        float a = 0.f, a2 = 0.f;
        for (int i = 0; i < 8; i++) {
            a += ss[i];
            a2 += ss2[i];
        }
        ss[0] = a;
        ss2[0] = a2;
    }
    __syncthreads();
    float mean = ss[0] * (1.f / CDIM);
    float var  = ss2[0] * (1.f / CDIM) - mean * mean;
    if (var < 0.f) var = 0.f;
    float inv = 1.f / (sqrtf(var) + 1e-6f);
    #pragma unroll
    for (int j = 0; j < 3; j++) {
        int i = threadIdx.x + j * 256;
        float v = gw[i] * (xv[j] - mean) * inv + gb[i];
        oh[(size_t)row * CDIM + i] = __float2half_rn(v);
    }
}

// ---------------- mma helpers (asm operand lists spaced) ----------------
__device__ __forceinline__ void ldsm_x4(uint32_t* r, const void* p)
{
    uint32_t addr = (uint32_t)__cvta_generic_to_shared(p);
    asm volatile("ldmatrix.sync.aligned.m8n8.x4.shared.b16 { %0, %1, %2, %3 }, [ %4 ];"
        : "=r"(r[0]), "=r"(r[1]), "=r"(r[2]), "=r"(r[3]) : "r"(addr));
}

__device__ __forceinline__ void ldsm_x4_t(uint32_t* r, const void* p)
{
    uint32_t addr = (uint32_t)__cvta_generic_to_shared(p);
    asm volatile("ldmatrix.sync.aligned.m8n8.x4.trans.shared.b16 { %0, %1, %2, %3 }, [ %4 ];"
        : "=r"(r[0]), "=r"(r[1]), "=r"(r[2]), "=r"(r[3]) : "r"(addr));
}

__device__ __forceinline__ void mma_f16(float* c, const uint32_t* a,
                                        uint32_t b0, uint32_t b1)
{
    asm volatile("mma.sync.aligned.m16n8k16.row.col.f32.f16.f16.f32 "
        "{ %0, %1, %2, %3 }, { %4, %5, %6, %7 }, { %8, %9 }, { %0, %1, %2, %3 };"
        : "+f"(c[0]), "+f"(c[1]), "+f"(c[2]), "+f"(c[3])
        : "r"(a[0]), "r"(a[1]), "r"(a[2]), "r"(a[3]), "r"(b0), "r"(b1));
}

// ---------------- 1-phase fp16 tensor-core GEMM, 3-stage cp.async ----------------
// C = A_hi @ B_hi + bias (+epilogue). fp32 accumulate.
// EPI: 1 = bias + GELU -> f16
//      2 = bias + residual -> fp32
//      3 = bias -> f16
#define HG_SMEM_BYTES (3 * (128 * 40 + 32 * 136) * 2)

#define HG_LOAD(s_, kk_) \
    cp16(&As[s_][rA0][cA0], Ahi + (size_t)(row0 + rA0) * K + (kk_) + cA0); \
    cp16(&As[s_][rA1][cA0], Ahi + (size_t)(row0 + rA1) * K + (kk_) + cA0); \
    cp16(&Bs[s_][rB0][cB0], Bhi + (size_t)((kk_) + rB0) * N + col0 + cB0); \
    cp16(&Bs[s_][rB1][cB0], Bhi + (size_t)((kk_) + rB1) * N + col0 + cB0); \
    CP_COMMIT()

template<int EPI>
__global__ __launch_bounds__(256, 2) void hgemm(
    const f16* __restrict__ Ahi,
    const f16* __restrict__ Bhi,
    const float* __restrict__ bias, const float* __restrict__ res,
    float* __restrict__ Cf, f16* __restrict__ Chi,
    int M, int N, int K)
{
    extern __shared__ f16 dsm[];
    f16 (*As)[128][40] = reinterpret_cast<f16 (*)[128][40]>(dsm);
    f16 (*Bs)[32][136] = reinterpret_cast<f16 (*)[32][136]>(dsm + 3 * 128 * 40);

    const int tid  = threadIdx.x;
    const int lane = tid & 31;
    const int warp = tid >> 5;
    const int wm = (warp >> 1) * 32;
    const int wn = (warp & 1) * 64;
    const int row0 = blockIdx.y * 128;
    const int col0 = blockIdx.x * 128;

    const int rA0 = tid >> 2;
    const int cA0 = (tid & 3) * 8;
    const int rA1 = rA0 + 64;
    const int rB0 = tid >> 4;
    const int cB0 = (tid & 15) * 8;
    const int rB1 = rB0 + 16;

    const int KT = K / 32;

    float acc[2][8][4];
    #pragma unroll
    for (int i = 0; i < 2; i++) {
        #pragma unroll
        for (int j = 0; j < 8; j++) {
            #pragma unroll
            for (int e = 0; e < 4; e++) {
                acc[i][j][e] = 0.f;
            }
        }
    }

    HG_LOAD(0, 0);
    HG_LOAD(1, 32);

    for (int it = 0; it < KT; ++it) {
        if (it + 1 < KT) {
            CP_WAIT1();
        } else {
            CP_WAIT0();
        }
        __syncthreads();
        if (it + 2 < KT) {
            HG_LOAD((it + 2) % 3, (it + 2) * 32);
        }
        const int s = it % 3;

        #pragma unroll
        for (int ks = 0; ks < 2; ++ks) {
            const int k0 = ks * 16;
            uint32_t af0[4];
            uint32_t af1[4];
            ldsm_x4(af0, &As[s][wm + (lane & 15)][k0 + (lane >> 4) * 8]);
            ldsm_x4(af1, &As[s][wm + 16 + (lane & 15)][k0 + (lane >> 4) * 8]);
            #pragma unroll
            for (int ni = 0; ni < 4; ++ni) {
                uint32_t bb[4];
                ldsm_x4_t(bb, &Bs[s][k0 + (lane & 15)][wn + ni * 16 + (lane >> 4) * 8]);
                mma_f16(acc[0][ni * 2 + 0], af0, bb[0], bb[1]);
                mma_f16(acc[0][ni * 2 + 1], af0, bb[2], bb[3]);
                mma_f16(acc[1][ni * 2 + 0], af1, bb[0], bb[1]);
                mma_f16(acc[1][ni * 2 + 1], af1, bb[2], bb[3]);
            }
        }
    }

    // epilogue: element pairs (e, e+1) are column-adjacent -> paired stores
    #pragma unroll
    for (int mi = 0; mi < 2; ++mi) {
        #pragma unroll
        for (int n8 = 0; n8 < 8; ++n8) {
            #pragma unroll
            for (int half = 0; half < 2; ++half) {
                int r = row0 + wm + mi * 16 + (lane >> 2) + half * 8;
                int c = col0 + wn + n8 * 8 + (lane & 3) * 2;
                float v0 = acc[mi][n8][half * 2 + 0] + bias[c];
                float v1 = acc[mi][n8][half * 2 + 1] + bias[c + 1];
                size_t off = (size_t)r * N + c;
                if (EPI == 1) {
                    v0 = 0.5f * v0 * (1.f + erff(v0 * 0.7071067811865475f));
                    v1 = 0.5f * v1 * (1.f + erff(v1 * 0.7071067811865475f));
                    *(uint32_t*)(Chi + off) = packh(v0, v1);
                } else if (EPI == 3) {
                    *(uint32_t*)(Chi + off) = packh(v0, v1);
                } else {
                    float2 rv = *(const float2*)(res + off);
                    float2 ov;
                    ov.x = v0 + rv.x;
                    ov.y = v1 + rv.y;
                    *(float2*)(Cf + off) = ov;
                }
            }
        }
    }
}

// ---------------- Tensor-core flash attention (causal, fp16) ----------------
// grid: (SEQ/64, NHEAD, BATCH), 128 threads = 4 warps; warp owns 16 query rows.
// 1-phase fp16 QK^T (scale folded into Q frags); PV in fp16; fp32 softmax state.
// K/V tiles double-buffered via cp.async; longest CTAs launch first.
// Warp-uniform skip of the oacc rescale when the running max is stable
// (co == 1.0 exactly -> bit-identical).
#define ATT_LOAD(s_, kt_) \
    _Pragma("unroll") \
    for (int li = 0; li < 4; li++) { \
        int e2 = tid + li * 128; \
        int r2 = e2 >> 3; \
        int c2 = (e2 & 7) * 8; \
        size_t goff2 = base + (size_t)((kt_) * 64 + r2) * QKVDIM + CDIM + h * HDIM + c2; \
        cp16(&KsH[s_][r2][c2], qkvh + goff2); \
        cp16(&Vs[s_][r2][c2], qkvh + goff2 + CDIM); \
    } \
    CP_COMMIT()

__global__ __launch_bounds__(128) void fattn_kernel(
    const f16* __restrict__ qkvh, f16* __restrict__ outh)
{
    __shared__ f16 Qs[64][72];
    __shared__ f16 KsH[2][64][72];
    __shared__ f16 Vs[2][64][72];

    const int b = blockIdx.z;
    const int h = blockIdx.y;
    const int qb = (SEQ / 64 - 1) - blockIdx.x;   // longest first
    const int tid = threadIdx.x;
    const int lane = tid & 31;
    const int warp = tid >> 5;
    const int row0 = qb * 64;

    const size_t base = (size_t)b * SEQ * QKVDIM;
    const __half2 sc2 = __floats2half2_rn(0.125f, 0.125f);

    // kick off first K/V tile load immediately
    ATT_LOAD(0, 0);

    // ---- stage Q, extract frags (scaled) ----
    #pragma unroll
    for (int i = 0; i < 4; i++) {
        int e = tid + i * 128;
        int r = e >> 3;
        int c = (e & 7) * 8;
        *(uint4*)&Qs[r][c] = *(const uint4*)(qkvh + base + (size_t)(row0 + r) * QKVDIM + h * HDIM + c);
    }
    __syncthreads();
    uint32_t qh[4][4];
    #pragma unroll
    for (int kf = 0; kf < 4; kf++) {
        ldsm_x4(qh[kf], &Qs[warp * 16 + (lane & 15)][kf * 16 + (lane >> 4) * 8]);
        #pragma unroll
        for (int e = 0; e < 4; e++) {
            __half2 t = *(__half2*)&qh[kf][e];
            t = __hmul2(t, sc2);
            qh[kf][e] = *(uint32_t*)&t;
        }
    }

    float oacc[8][4];
    #pragma unroll
    for (int nb = 0; nb < 8; nb++) {
        #pragma unroll
        for (int e = 0; e < 4; e++) {
            oacc[nb][e] = 0.f;
        }
    }
    float m1 = -1e30f, m2 = -1e30f;
    float l1 = 0.f, l2 = 0.f;

    const int r1g = row0 + warp * 16 + (lane >> 2);
    const int r2g = r1g + 8;

    for (int kt = 0; kt <= qb; kt++) {
        const int j0g = kt * 64;
        CP_WAIT0();
        __syncthreads();
        if (kt + 1 <= qb) {
            ATT_LOAD((kt + 1) & 1, kt + 1);
        }
        const int s = kt & 1;

        // ---- S = Q K^T (1 phase, scale pre-folded) ----
        float sacc[8][4];
        #pragma unroll
        for (int nb = 0; nb < 8; nb++) {
            #pragma unroll
            for (int e = 0; e < 4; e++) {
                sacc[nb][e] = 0.f;
            }
        }
        #pragma unroll
        for (int kf = 0; kf < 4; kf++) {
            const int d0 = kf * 16;
            #pragma unroll
            for (int p = 0; p < 4; p++) {
                const int j0 = p * 16;
                uint32_t bh[4];
                ldsm_x4(bh, &KsH[s][j0 + ((lane >> 4) << 3) + (lane & 7)][d0 + (((lane >> 3) & 1) << 3)]);
                mma_f16(sacc[p * 2 + 0], qh[kf], bh[0], bh[1]);
                mma_f16(sacc[p * 2 + 1], qh[kf], bh[2], bh[3]);
            }
        }

        // ---- causal mask (diagonal tile only) ----
        if (kt == qb) {
            #pragma unroll
            for (int nb = 0; nb < 8; nb++) {
                int jg = j0g + nb * 8 + (lane & 3) * 2;
                if (jg     > r1g) sacc[nb][0] = -1e30f;
                if (jg + 1 > r1g) sacc[nb][1] = -1e30f;
                if (jg     > r2g) sacc[nb][2] = -1e30f;
                if (jg + 1 > r2g) sacc[nb][3] = -1e30f;
            }
        }

        // ---- online softmax ----
        float mx1 = -1e30f, mx2 = -1e30f;
        #pragma unroll
        for (int nb = 0; nb < 8; nb++) {
            mx1 = fmaxf(mx1, fmaxf(sacc[nb][0], sacc[nb][1]));
            mx2 = fmaxf(mx2, fmaxf(sacc[nb][2], sacc[nb][3]));
        }
        mx1 = fmaxf(mx1, __shfl_xor_sync(0xFFFFFFFFu, mx1, 1));
        mx1 = fmaxf(mx1, __shfl_xor_sync(0xFFFFFFFFu, mx1, 2));
        mx2 = fmaxf(mx2, __shfl_xor_sync(0xFFFFFFFFu, mx2, 1));
        mx2 = fmaxf(mx2, __shfl_xor_sync(0xFFFFFFFFu, mx2, 2));

        const uint32_t stable = __all_sync(0xFFFFFFFFu, (mx1 <= m1) && (mx2 <= m2));

        if (!stable) {
            float om1 = m1;
            float om2 = m2;
            m1 = fmaxf(m1, mx1);
            m2 = fmaxf(m2, mx2);
            float co1 = __expf(om1 - m1);
            float co2 = __expf(om2 - m2);
            l1 *= co1;
            l2 *= co2;
            #pragma unroll
            for (int nb = 0; nb < 8; nb++) {
                oacc[nb][0] *= co1;
                oacc[nb][1] *= co1;
                oacc[nb][2] *= co2;
                oacc[nb][3] *= co2;
            }
        }

        uint32_t pa1[8];
        uint32_t pa2[8];
        float ps1 = 0.f, ps2 = 0.f;
        #pragma unroll
        for (int nb = 0; nb < 8; nb++) {
            float p0 = __expf(sacc[nb][0] - m1);
            float p1 = __expf(sacc[nb][1] - m1);
            float p2 = __expf(sacc[nb][2] - m2);
            float p3 = __expf(sacc[nb][3] - m2);
            ps1 += p0 + p1;
            ps2 += p2 + p3;
            pa1[nb] = packh(p0, p1);
            pa2[nb] = packh(p2, p3);
        }
        l1 += ps1;
        l2 += ps2;

        // ---- O += P V ----
        #pragma unroll
        for (int kf = 0; kf < 4; kf++) {
            uint32_t af[4];
            af[0] = pa1[kf * 2];
            af[1] = pa2[kf * 2];
            af[2] = pa1[kf * 2 + 1];
            af[3] = pa2[kf * 2 + 1];
            #pragma unroll
            for (int pd = 0; pd < 4; pd++) {
                uint32_t bb[4];
                ldsm_x4_t(bb, &Vs[s][kf * 16 + (lane & 15)][pd * 16 + (lane >> 4) * 8]);
                mma_f16(oacc[pd * 2 + 0], af, bb[0], bb[1]);
                mma_f16(oacc[pd * 2 + 1], af, bb[2], bb[3]);
            }
        }
    }

    // ---- finalize ----
    l1 += __shfl_xor_sync(0xFFFFFFFFu, l1, 1);
    l1 += __shfl_xor_sync(0xFFFFFFFFu, l1, 2);
    l2 += __shfl_xor_sync(0xFFFFFFFFu, l2, 1);
    l2 += __shfl_xor_sync(0xFFFFFFFFu, l2, 2);
    float inv1 = 1.f / l1;
    float inv2 = 1.f / l2;

    size_t ob1 = (size_t)(b * SEQ + r1g) * CDIM + h * HDIM;
    size_t ob2 = (size_t)(b * SEQ + r2g) * CDIM + h * HDIM;
    #pragma unroll
    for (int nb = 0; nb < 8; nb++) {
        int c = nb * 8 + (lane & 3) * 2;
        *(uint32_t*)(outh + ob1 + c) = packh(oacc[nb][0] * inv1, oacc[nb][1] * inv1);
        *(uint32_t*)(outh + ob2 + c) = packh(oacc[nb][2] * inv2, oacc[nb][3] * inv2);
    }
}

// ---------------- launch ----------------
extern "C" void kernel_launch(void* const* d_in, const int* in_sizes, int n_in,
                              void* d_out, int out_size)
{
    const float* x           = (const float*)d_in[0];
    const float* ln1_w       = (const float*)d_in[1];
    const float* ln1_b       = (const float*)d_in[2];
    const float* W_attn      = (const float*)d_in[3];
    const float* b_attn      = (const float*)d_in[4];
    const float* W_attn_proj = (const float*)d_in[5];
    const float* b_attn_proj = (const float*)d_in[6];
    const float* ln2_w       = (const float*)d_in[7];
    const float* ln2_b       = (const float*)d_in[8];
    const float* W_fc        = (const float*)d_in[9];
    const float* b_fc        = (const float*)d_in[10];
    const float* W_mlp_proj  = (const float*)d_in[11];
    const float* b_mlp_proj  = (const float*)d_in[12];
    float* out = (float*)d_out;

    f16 *p_lnh, *p_qkvh, *p_atth, *p_fch;
    f16 *p_wah, *p_wph, *p_wfh, *p_wmh;
    float *p_x1;
    cudaGetSymbolAddress((void**)&p_lnh,  g_lnh);
    cudaGetSymbolAddress((void**)&p_qkvh, g_qkvh);
    cudaGetSymbolAddress((void**)&p_atth, g_atth);
    cudaGetSymbolAddress((void**)&p_x1,   g_x1);
    cudaGetSymbolAddress((void**)&p_fch,  g_fch);
    cudaGetSymbolAddress((void**)&p_wah,  g_wah);
    cudaGetSymbolAddress((void**)&p_wph,  g_wph);
    cudaGetSymbolAddress((void**)&p_wfh,  g_wfh);
    cudaGetSymbolAddress((void**)&p_wmh,  g_wmh);

    cudaFuncSetAttribute(hgemm<1>, cudaFuncAttributeMaxDynamicSharedMemorySize, HG_SMEM_BYTES);
    cudaFuncSetAttribute(hgemm<2>, cudaFuncAttributeMaxDynamicSharedMemorySize, HG_SMEM_BYTES);
    cudaFuncSetAttribute(hgemm<3>, cudaFuncAttributeMaxDynamicSharedMemorySize, HG_SMEM_BYTES);

    cvt_kernel<<<(CDIM * QKVDIM / 8 + 255) / 256, 256>>>(W_attn,      p_wah, CDIM * QKVDIM / 8);
    cvt_kernel<<<(CDIM * CDIM   / 8 + 255) / 256, 256>>>(W_attn_proj, p_wph, CDIM * CDIM / 8);
    cvt_kernel<<<(CDIM * FCDIM  / 8 + 255) / 256, 256>>>(W_fc,        p_wfh, CDIM * FCDIM / 8);
    cvt_kernel<<<(FCDIM * CDIM  / 8 + 255) / 256, 256>>>(W_mlp_proj,  p_wmh, FCDIM * CDIM / 8);

    ln_kernel<<<MROWS, 256>>>(x, ln1_w, ln1_b, p_lnh);

    hgemm<3><<<dim3(QKVDIM / 128, MROWS / 128), 256, HG_SMEM_BYTES>>>(p_lnh, p_wah,
        b_attn, (const float*)0, (float*)0, p_qkvh, MROWS, QKVDIM, CDIM);

    fattn_kernel<<<dim3(SEQ / 64, NHEAD, BATCH), 128>>>(p_qkvh, p_atth);

    hgemm<2><<<dim3(CDIM / 128, MROWS / 128), 256, HG_SMEM_BYTES>>>(p_atth, p_wph,
        b_attn_proj, x, p_x1, (f16*)0, MROWS, CDIM, CDIM);

    ln_kernel<<<MROWS, 256>>>(p_x1, ln2_w, ln2_b, p_lnh);

    hgemm<1><<<dim3(FCDIM / 128, MROWS / 128), 256, HG_SMEM_BYTES>>>(p_lnh, p_wfh,
        b_fc, (const float*)0, (float*)0, p_fch, MROWS, FCDIM, CDIM);

    hgemm<2><<<dim3(CDIM / 128, MROWS / 128), 256, HG_SMEM_BYTES>>>(p_fch, p_wmh,
        b_mlp_proj, p_x1, out, (f16*)0, MROWS, CDIM, FCDIM);
}